// round 5
// baseline (speedup 1.0000x reference)
#include <cuda_runtime.h>
#include <cuda_bf16.h>
#include <cstdint>
#include <math.h>

#define D_MODEL 1024
#define D_VOCAB 32000
#define NB 4
#define SEQ 1024
#define BT (NB * SEQ)
#define NLAYERS 6
#define BTV ((long)BT * D_VOCAB)

typedef __nv_bfloat16 bf16;
typedef __nv_bfloat162 bf162;

// ---------------- scratch (device globals) ----------------------------------
__device__ float g_z [BT * D_MODEL];
__device__ float g_v [BT * D_MODEL];
__device__ float g_o [BT * D_MODEL];
__device__ float g_s [NB * SEQ * SEQ];
__device__ float g_nll[BT];

__device__ bf16 g_ylnh[BT * D_MODEL];
__device__ bf16 g_ylnl[BT * D_MODEL];
__device__ bf16 g_qh  [BT * D_MODEL];
__device__ bf16 g_ql  [BT * D_MODEL];
__device__ bf16 g_kh  [BT * D_MODEL];
__device__ bf16 g_kl  [BT * D_MODEL];
__device__ bf16 g_sh  [NB * SEQ * SEQ];
__device__ bf16 g_sl  [NB * SEQ * SEQ];
__device__ bf16 g_vTh [BT * D_MODEL];
__device__ bf16 g_vTl [BT * D_MODEL];
__device__ bf16 g_hh  [BT * D_MODEL];
__device__ bf16 g_hl  [BT * D_MODEL];
__device__ bf16 g_zh  [BT * D_MODEL];
__device__ bf16 g_zl  [BT * D_MODEL];
__device__ bf16 g_ench[(long)D_VOCAB * D_MODEL];
__device__ bf16 g_encl[(long)D_VOCAB * D_MODEL];
__device__ bf16 g_wth [5 * D_MODEL * D_MODEL];
__device__ bf16 g_wtl [5 * D_MODEL * D_MODEL];

// ---------------- helpers ----------------------------------------------------
__device__ __forceinline__ uint32_t smem_u32(const void* p) {
    uint32_t a;
    asm("{ .reg .u64 t; cvta.to.shared.u64 t, %1; cvt.u32.u64 %0, t; }" : "=r"(a) : "l"(p));
    return a;
}
__device__ __forceinline__ void split1(float x, bf16& h, bf16& l) {
    h = __float2bfloat16(x);
    l = __float2bfloat16(x - __bfloat162float(h));
}
__device__ __forceinline__ void ldsm4(uint32_t addr, uint32_t& r0, uint32_t& r1,
                                      uint32_t& r2, uint32_t& r3) {
    asm volatile("ldmatrix.sync.aligned.m8n8.x4.shared.b16 {%0,%1,%2,%3}, [%4];"
                 : "=r"(r0), "=r"(r1), "=r"(r2), "=r"(r3) : "r"(addr));
}
__device__ __forceinline__ void mma_bf16(float* c, uint32_t a0, uint32_t a1,
                                         uint32_t a2, uint32_t a3,
                                         uint32_t b0, uint32_t b1) {
    asm volatile(
        "mma.sync.aligned.m16n8k16.row.col.f32.bf16.bf16.f32 "
        "{%0,%1,%2,%3}, {%4,%5,%6,%7}, {%8,%9}, {%0,%1,%2,%3};"
        : "+f"(c[0]), "+f"(c[1]), "+f"(c[2]), "+f"(c[3])
        : "r"(a0), "r"(a1), "r"(a2), "r"(a3), "r"(b0), "r"(b1));
}
#define CP16(dst, src) \
    asm volatile("cp.async.cg.shared.global [%0], [%1], 16;" :: "r"(dst), "l"(src))
#define CP_COMMIT() asm volatile("cp.async.commit_group;" ::: "memory")
#define CP_WAIT1()  asm volatile("cp.async.wait_group 1;" ::: "memory")
#define CP_WAIT0()  asm volatile("cp.async.wait_group 0;" ::: "memory")

// ---------------- bf16-split GEMM NT: C = alpha * (Ah+Al)(Bh+Bl)^T -----------
// A: M x K row-major (hi/lo), B: N x K row-major (hi/lo)
// flags: 1=relu, 2=accumulate into C fp32, 4=bias, 8=write split Ch/Cl, 16=write C fp32
// grid (M/128, N/128, batch), 256 threads. K%32==0.
#define STAGE_BYTES 32768
__global__ __launch_bounds__(256) void gemm_bs(
    const bf16* __restrict__ Ah, const bf16* __restrict__ Al,
    const bf16* __restrict__ Bh, const bf16* __restrict__ Bl,
    const float* __restrict__ bias, float* __restrict__ C,
    bf16* __restrict__ Ch, bf16* __restrict__ Cl,
    int M, int N, int K, long sA, long sB, long sC, float alpha, int flags) {

    extern __shared__ __align__(16) uint8_t sm[];   // 2 stages x (Ah|Al|Bh|Bl) 8KB each

    Ah += (long)blockIdx.z * sA;  Al += (long)blockIdx.z * sA;
    Bh += (long)blockIdx.z * sB;  Bl += (long)blockIdx.z * sB;
    C  += (long)blockIdx.z * sC;
    if (Ch) { Ch += (long)blockIdx.z * sC; Cl += (long)blockIdx.z * sC; }

    const int tid  = threadIdx.x;
    const int wid  = tid >> 5;
    const int lane = tid & 31;
    const int warp_m = wid & 3;
    const int warp_n = wid >> 2;
    const int row0 = blockIdx.x * 128;
    const int col0 = blockIdx.y * 128;

    const uint32_t sbase = smem_u32(sm);

    const int lr = tid >> 1;           // 0..127
    const int lq = tid & 1;
    const int swz = (lr >> 1) & 3;
    const bf16* Ahp = Ah + (long)(row0 + lr) * K;
    const bf16* Alp = Al + (long)(row0 + lr) * K;
    const bf16* Bhp = Bh + (long)(col0 + lr) * K;
    const bf16* Blp = Bl + (long)(col0 + lr) * K;

    float acc[2][8][4];
    #pragma unroll
    for (int mb = 0; mb < 2; mb++)
        #pragma unroll
        for (int nb = 0; nb < 8; nb++)
            #pragma unroll
            for (int i = 0; i < 4; i++) acc[mb][nb][i] = 0.f;

    // ---- async tile loader: one K=32 tile into stage st ----
    auto load_tile = [&](int k0, int st) {
        uint32_t sb = sbase + st * STAGE_BYTES;
        #pragma unroll
        for (int j = 0; j < 2; j++) {
            int c = lq * 2 + j;
            uint32_t off = (uint32_t)(lr * 64 + (c ^ swz) * 16);
            CP16(sb + off,         Ahp + k0 + c * 8);
            CP16(sb + 8192 + off,  Alp + k0 + c * 8);
            CP16(sb + 16384 + off, Bhp + k0 + c * 8);
            CP16(sb + 24576 + off, Blp + k0 + c * 8);
        }
    };

    load_tile(0, 0);
    CP_COMMIT();
    const int KT = K >> 5;

    for (int kt = 0; kt < KT; kt++) {
        if (kt + 1 < KT) {
            load_tile((kt + 1) << 5, (kt + 1) & 1);
            CP_COMMIT();
            CP_WAIT1();
        } else {
            CP_WAIT0();
        }
        __syncthreads();

        uint32_t sb = sbase + (kt & 1) * STAGE_BYTES;
        #pragma unroll
        for (int kc = 0; kc < 2; kc++) {
            uint32_t bh[8][2], bl[8][2];
            #pragma unroll
            for (int nb4 = 0; nb4 < 4; nb4++) {
                int nrow  = warp_n * 64 + nb4 * 16 + (lane & 15);
                int chunk = kc * 2 + (lane >> 4);
                uint32_t off = (uint32_t)(nrow * 64 + (chunk ^ ((nrow >> 1) & 3)) * 16);
                uint32_t r0, r1, r2, r3;
                ldsm4(sb + 16384 + off, r0, r1, r2, r3);
                bh[nb4 * 2][0] = r0; bh[nb4 * 2 + 1][0] = r1;
                bh[nb4 * 2][1] = r2; bh[nb4 * 2 + 1][1] = r3;
                ldsm4(sb + 24576 + off, r0, r1, r2, r3);
                bl[nb4 * 2][0] = r0; bl[nb4 * 2 + 1][0] = r1;
                bl[nb4 * 2][1] = r2; bl[nb4 * 2 + 1][1] = r3;
            }
            #pragma unroll
            for (int mb = 0; mb < 2; mb++) {
                int mrow  = warp_m * 32 + mb * 16 + (lane & 15);
                int chunk = kc * 2 + (lane >> 4);
                uint32_t off = (uint32_t)(mrow * 64 + (chunk ^ ((mrow >> 1) & 3)) * 16);
                uint32_t ah0, ah1, ah2, ah3, al0, al1, al2, al3;
                ldsm4(sb + off, ah0, ah1, ah2, ah3);
                ldsm4(sb + 8192 + off, al0, al1, al2, al3);
                #pragma unroll
                for (int nb = 0; nb < 8; nb++) {
                    mma_bf16(acc[mb][nb], ah0, ah1, ah2, ah3, bh[nb][0], bh[nb][1]);
                    mma_bf16(acc[mb][nb], ah0, ah1, ah2, ah3, bl[nb][0], bl[nb][1]);
                    mma_bf16(acc[mb][nb], al0, al1, al2, al3, bh[nb][0], bh[nb][1]);
                }
            }
        }
        __syncthreads();
    }

    // ---- epilogue ----
    #pragma unroll
    for (int mb = 0; mb < 2; mb++) {
        #pragma unroll
        for (int nb = 0; nb < 8; nb++) {
            int m0 = row0 + warp_m * 32 + mb * 16 + (lane >> 2);
            int n0 = col0 + warp_n * 64 + nb * 8 + (lane & 3) * 2;
            #pragma unroll
            for (int half = 0; half < 2; half++) {
                int m = m0 + half * 8;
                float v0 = acc[mb][nb][half * 2 + 0] * alpha;
                float v1 = acc[mb][nb][half * 2 + 1] * alpha;
                if (flags & 4) { v0 += bias[n0]; v1 += bias[n0 + 1]; }
                if (flags & 1) { v0 = fmaxf(v0, 0.f); v1 = fmaxf(v1, 0.f); }
                long idx = (long)m * N + n0;
                if (flags & 2) { float2 o = *(float2*)(C + idx); v0 += o.x; v1 += o.y; }
                if (flags & 16) *(float2*)(C + idx) = make_float2(v0, v1);
                if (flags & 8) {
                    bf16 h0, l0, h1, l1;
                    split1(v0, h0, l0); split1(v1, h1, l1);
                    bf162 hv; hv.x = h0; hv.y = h1;
                    bf162 lv; lv.x = l0; lv.y = l1;
                    *(bf162*)(Ch + idx) = hv;
                    *(bf162*)(Cl + idx) = lv;
                }
            }
        }
    }
}

// ---------------- transpose+split: dst(C x R) = split(src(R x C)^T) ----------
__global__ void transpose_split(const float* __restrict__ src, bf16* __restrict__ dh,
                                bf16* __restrict__ dl, int R, int Ccols) {
    __shared__ float t[32][33];
    long ofs = (long)blockIdx.z * R * Ccols;
    src += ofs; dh += ofs; dl += ofs;
    int bx = blockIdx.x * 32, by = blockIdx.y * 32;
    int x = bx + threadIdx.x;
    #pragma unroll
    for (int j = 0; j < 32; j += 8) {
        int y = by + threadIdx.y + j;
        t[threadIdx.y + j][threadIdx.x] = src[(long)y * Ccols + x];
    }
    __syncthreads();
    x = by + threadIdx.x;
    #pragma unroll
    for (int j = 0; j < 32; j += 8) {
        int y = bx + threadIdx.y + j;
        bf16 h, l;
        split1(t[threadIdx.x][threadIdx.y + j], h, l);
        dh[(long)y * R + x] = h;
        dl[(long)y * R + x] = l;
    }
}

// ---------------- plain split: fp32 -> hi/lo bf16 ----------------------------
__global__ void split_kernel(const float* __restrict__ src, bf16* __restrict__ dh,
                             bf16* __restrict__ dl, long n) {
    long i = (long)blockIdx.x * blockDim.x + threadIdx.x;
    long stride = (long)gridDim.x * blockDim.x;
    for (; i < n; i += stride) {
        bf16 h, l;
        split1(src[i], h, l);
        dh[i] = h; dl[i] = l;
    }
}

// ---------------- embedding gather ------------------------------------------
__global__ void embed_kernel(const int* __restrict__ x, const float* __restrict__ enc,
                             float* __restrict__ z) {
    int row = blockIdx.x;
    int tok = x[row];
    const float4* src = (const float4*)(enc + (long)tok * D_MODEL);
    float4* dst = (float4*)(z + (long)row * D_MODEL);
    for (int i = threadIdx.x; i < D_MODEL / 4; i += blockDim.x) dst[i] = src[i];
}

// ---------------- (buggy) LayerNorm -> split bf16 output ---------------------
__global__ void ln_kernel(const float* __restrict__ in, const float* __restrict__ gamma,
                          const float* __restrict__ beta, bf16* __restrict__ outh,
                          bf16* __restrict__ outl) {
    int row = blockIdx.x;
    const float* xr = in + (long)row * D_MODEL;
    __shared__ float red[256];
    int tid = threadIdx.x;

    float s = 0.f;
    for (int i = tid; i < D_MODEL; i += 256) s += xr[i];
    red[tid] = s; __syncthreads();
    #pragma unroll
    for (int o = 128; o > 0; o >>= 1) { if (tid < o) red[tid] += red[tid + o]; __syncthreads(); }
    float mu = red[0] / (float)D_MODEL;
    __syncthreads();

    float s2 = 0.f;
    for (int i = tid; i < D_MODEL; i += 256) { float d = xr[i] - mu; s2 += d * d; }
    red[tid] = s2; __syncthreads();
    #pragma unroll
    for (int o = 128; o > 0; o >>= 1) { if (tid < o) red[tid] += red[tid + o]; __syncthreads(); }
    float var = red[0] / (float)(D_MODEL - 1);
    float shift = mu * rsqrtf(var);

    bf16* oh = outh + (long)row * D_MODEL;
    bf16* ol = outl + (long)row * D_MODEL;
    for (int i = tid; i < D_MODEL; i += 256) {
        float v = (xr[i] - shift) * gamma[i] + beta[i];
        bf16 h, l; split1(v, h, l);
        oh[i] = h; ol[i] = l;
    }
}

// ---------------- row softmax over SEQ -> split bf16 output ------------------
__global__ void softmax_kernel(float* __restrict__ s, bf16* __restrict__ outh,
                               bf16* __restrict__ outl) {
    int row = blockIdx.x;
    float* r = s + (long)row * SEQ;
    __shared__ float red[256];
    int tid = threadIdx.x;

    float m = -1e30f;
    for (int i = tid; i < SEQ; i += 256) m = fmaxf(m, r[i]);
    red[tid] = m; __syncthreads();
    #pragma unroll
    for (int o = 128; o > 0; o >>= 1) { if (tid < o) red[tid] = fmaxf(red[tid], red[tid + o]); __syncthreads(); }
    float mx = red[0]; __syncthreads();

    float sum = 0.f;
    for (int i = tid; i < SEQ; i += 256) { float e = expf(r[i] - mx); r[i] = e; sum += e; }
    red[tid] = sum; __syncthreads();
    #pragma unroll
    for (int o = 128; o > 0; o >>= 1) { if (tid < o) red[tid] += red[tid + o]; __syncthreads(); }
    float inv = 1.f / red[0];

    bf16* oh = outh + (long)row * SEQ;
    bf16* ol = outl + (long)row * SEQ;
    for (int i = tid; i < SEQ; i += 256) {
        float v = r[i] * inv;
        bf16 h, l; split1(v, h, l);
        oh[i] = h; ol[i] = l;
    }
}

// ---------------- per-row NLL over V=32000 ----------------------------------
__global__ void nll_kernel(const float* __restrict__ logits, const int* __restrict__ y,
                           float* __restrict__ nll) {
    int row = blockIdx.x;
    const float* r = logits + (long)row * D_VOCAB;
    __shared__ float red[256];
    int tid = threadIdx.x;

    float m = -1e30f;
    for (int i = tid; i < D_VOCAB; i += 256) m = fmaxf(m, r[i]);
    red[tid] = m; __syncthreads();
    #pragma unroll
    for (int o = 128; o > 0; o >>= 1) { if (tid < o) red[tid] = fmaxf(red[tid], red[tid + o]); __syncthreads(); }
    float mx = red[0]; __syncthreads();

    float s = 0.f;
    for (int i = tid; i < D_VOCAB; i += 256) s += expf(r[i] - mx);
    red[tid] = s; __syncthreads();
    #pragma unroll
    for (int o = 128; o > 0; o >>= 1) { if (tid < o) red[tid] += red[tid + o]; __syncthreads(); }

    if (tid == 0) nll[row] = (mx + logf(red[0])) - r[y[row]];
}

__global__ void loss_reduce_kernel(const float* __restrict__ nll, float* __restrict__ out,
                                   long ofs) {
    __shared__ float red[256];
    int tid = threadIdx.x;
    float s = 0.f;
    for (int i = tid; i < BT; i += 256) s += nll[i];
    red[tid] = s; __syncthreads();
    #pragma unroll
    for (int o = 128; o > 0; o >>= 1) { if (tid < o) red[tid] += red[tid + o]; __syncthreads(); }
    if (tid == 0) out[ofs] = red[0] / (float)BT;
}

// ---------------- driver -----------------------------------------------------
extern "C" void kernel_launch(void* const* d_in, const int* in_sizes, int n_in,
                              void* d_out, int out_size) {
    (void)in_sizes; (void)n_in;
    const int*   x   = (const int*)  d_in[0];
    const int*   y   = (const int*)  d_in[1];
    const float* enc = (const float*)d_in[2];
    const float* g1  = (const float*)d_in[3];
    const float* b1  = (const float*)d_in[4];
    const float* wq  = (const float*)d_in[5];
    const float* wk  = (const float*)d_in[6];
    const float* wv  = (const float*)d_in[7];
    const float* g2  = (const float*)d_in[8];
    const float* b2  = (const float*)d_in[9];
    const float* w1  = (const float*)d_in[10];
    const float* bb1 = (const float*)d_in[11];
    const float* w2  = (const float*)d_in[12];
    const float* bb2 = (const float*)d_in[13];
    float* out = (float*)d_out;

    float *z, *v, *o, *s, *nll;
    bf16 *ylnh, *ylnl, *qh, *ql, *kh, *kl, *sh, *sl, *vTh, *vTl, *hh, *hl;
    bf16 *zh, *zl, *ench, *encl, *wth, *wtl;
    cudaGetSymbolAddress((void**)&z,   g_z);
    cudaGetSymbolAddress((void**)&v,   g_v);
    cudaGetSymbolAddress((void**)&o,   g_o);
    cudaGetSymbolAddress((void**)&s,   g_s);
    cudaGetSymbolAddress((void**)&nll, g_nll);
    cudaGetSymbolAddress((void**)&ylnh, g_ylnh);
    cudaGetSymbolAddress((void**)&ylnl, g_ylnl);
    cudaGetSymbolAddress((void**)&qh, g_qh);
    cudaGetSymbolAddress((void**)&ql, g_ql);
    cudaGetSymbolAddress((void**)&kh, g_kh);
    cudaGetSymbolAddress((void**)&kl, g_kl);
    cudaGetSymbolAddress((void**)&sh, g_sh);
    cudaGetSymbolAddress((void**)&sl, g_sl);
    cudaGetSymbolAddress((void**)&vTh, g_vTh);
    cudaGetSymbolAddress((void**)&vTl, g_vTl);
    cudaGetSymbolAddress((void**)&hh, g_hh);
    cudaGetSymbolAddress((void**)&hl, g_hl);
    cudaGetSymbolAddress((void**)&zh, g_zh);
    cudaGetSymbolAddress((void**)&zl, g_zl);
    cudaGetSymbolAddress((void**)&ench, g_ench);
    cudaGetSymbolAddress((void**)&encl, g_encl);
    cudaGetSymbolAddress((void**)&wth, g_wth);
    cudaGetSymbolAddress((void**)&wtl, g_wtl);

    static int smem_set = 0;
    if (!smem_set) {
        cudaFuncSetAttribute(gemm_bs, cudaFuncAttributeMaxDynamicSharedMemorySize,
                             2 * STAGE_BYTES);
        smem_set = 1;
    }
    const int GS = 2 * STAGE_BYTES;

    const long DD = (long)D_MODEL * D_MODEL;
    const long SD = (long)SEQ * D_MODEL;
    const long SS = (long)SEQ * SEQ;
    bf16* wqTh = wth + 0 * DD; bf16* wqTl = wtl + 0 * DD;
    bf16* wkTh = wth + 1 * DD; bf16* wkTl = wtl + 1 * DD;
    bf16* wvTh = wth + 2 * DD; bf16* wvTl = wtl + 2 * DD;
    bf16* w1Th = wth + 3 * DD; bf16* w1Tl = wtl + 3 * DD;
    bf16* w2Th = wth + 4 * DD; bf16* w2Tl = wtl + 4 * DD;

    dim3 tgrid(D_MODEL / 32, D_MODEL / 32, 1);
    dim3 tblk(32, 8);
    transpose_split<<<tgrid, tblk>>>(wq, wqTh, wqTl, D_MODEL, D_MODEL);
    transpose_split<<<tgrid, tblk>>>(wk, wkTh, wkTl, D_MODEL, D_MODEL);
    transpose_split<<<tgrid, tblk>>>(wv, wvTh, wvTl, D_MODEL, D_MODEL);
    transpose_split<<<tgrid, tblk>>>(w1, w1Th, w1Tl, D_MODEL, D_MODEL);
    transpose_split<<<tgrid, tblk>>>(w2, w2Th, w2Tl, D_MODEL, D_MODEL);
    split_kernel<<<1024, 256>>>(enc, ench, encl, (long)D_VOCAB * D_MODEL);

    embed_kernel<<<BT, 256>>>(x, enc, z);

    dim3 grid_proj(BT / 128, D_MODEL / 128);       // (32, 8)
    dim3 grid_attn(SEQ / 128, SEQ / 128, NB);      // (8, 8, 4)
    dim3 tgrid_v(D_MODEL / 32, SEQ / 32, NB);

    for (int layer = 0; layer < NLAYERS; layer++) {
        ln_kernel<<<BT, 256>>>(z, g1, b1, ylnh, ylnl);

        // Q,K -> split-only outputs; V -> fp32 (for transpose)
        gemm_bs<<<grid_proj, 256, GS>>>(ylnh, ylnl, wqTh, wqTl, nullptr, nullptr, qh, ql,
                                        BT, D_MODEL, D_MODEL, 0, 0, 0, 1.f, 8);
        gemm_bs<<<grid_proj, 256, GS>>>(ylnh, ylnl, wkTh, wkTl, nullptr, nullptr, kh, kl,
                                        BT, D_MODEL, D_MODEL, 0, 0, 0, 1.f, 8);
        gemm_bs<<<grid_proj, 256, GS>>>(ylnh, ylnl, wvTh, wvTl, nullptr, v, nullptr, nullptr,
                                        BT, D_MODEL, D_MODEL, 0, 0, 0, 1.f, 16);

        // S = (Q K^T)/32 -> fp32
        gemm_bs<<<grid_attn, 256, GS>>>(qh, ql, kh, kl, nullptr, s, nullptr, nullptr,
                                        SEQ, SEQ, D_MODEL, SD, SD, SS, 0.03125f, 16);

        softmax_kernel<<<NB * SEQ, 256>>>(s, sh, sl);

        transpose_split<<<tgrid_v, tblk>>>(v, vTh, vTl, SEQ, D_MODEL);

        // O = S V -> fp32
        gemm_bs<<<grid_attn, 256, GS>>>(sh, sl, vTh, vTl, nullptr, o, nullptr, nullptr,
                                        SEQ, D_MODEL, SEQ, SS, SD, SD, 1.f, 16);

        ln_kernel<<<BT, 256>>>(o, g2, b2, ylnh, ylnl);

        // H = relu(Y W1 + b1) -> split-only
        gemm_bs<<<grid_proj, 256, GS>>>(ylnh, ylnl, w1Th, w1Tl, bb1, nullptr, hh, hl,
                                        BT, D_MODEL, D_MODEL, 0, 0, 0, 1.f, 8 | 4 | 1);
        // Z += H W2 + b2 -> fp32 accumulate
        gemm_bs<<<grid_proj, 256, GS>>>(hh, hl, w2Th, w2Tl, bb2, z, nullptr, nullptr,
                                        BT, D_MODEL, D_MODEL, 0, 0, 0, 1.f, 16 | 4 | 2);
    }

    split_kernel<<<512, 256>>>(z, zh, zl, (long)BT * D_MODEL);

    // logits = Z enc^T  (enc already (V, D) row-major)
    dim3 grid_logits(BT / 128, D_VOCAB / 128);     // (32, 250)
    gemm_bs<<<grid_logits, 256, GS>>>(zh, zl, ench, encl, nullptr, out, nullptr, nullptr,
                                      BT, D_VOCAB, D_MODEL, 0, 0, 0, 1.f, 16);

    nll_kernel<<<BT, 256>>>(out, y, nll);
    if ((long)out_size > BTV)
        loss_reduce_kernel<<<1, 256>>>(nll, out, BTV);
}

// round 6
// speedup vs baseline: 1.1398x; 1.1398x over previous
#include <cuda_runtime.h>
#include <cuda_bf16.h>
#include <cstdint>
#include <math.h>

#define D_MODEL 1024
#define D_VOCAB 32000
#define NB 4
#define SEQ 1024
#define BT (NB * SEQ)
#define NLAYERS 6
#define BTV ((long)BT * D_VOCAB)

typedef __nv_bfloat16 bf16;
typedef __nv_bfloat162 bf162;

// ---------------- scratch (device globals) ----------------------------------
__device__ float g_z [BT * D_MODEL];
__device__ float g_v [BT * D_MODEL];
__device__ float g_o [BT * D_MODEL];
__device__ float g_s [NB * SEQ * SEQ];
__device__ float g_nll[BT];

__device__ bf16 g_ylnh[BT * D_MODEL];
__device__ bf16 g_ylnl[BT * D_MODEL];
__device__ bf16 g_qh  [BT * D_MODEL];
__device__ bf16 g_ql  [BT * D_MODEL];
__device__ bf16 g_kh  [BT * D_MODEL];
__device__ bf16 g_kl  [BT * D_MODEL];
__device__ bf16 g_sh  [NB * SEQ * SEQ];
__device__ bf16 g_sl  [NB * SEQ * SEQ];
__device__ bf16 g_vTh [BT * D_MODEL];
__device__ bf16 g_vTl [BT * D_MODEL];
__device__ bf16 g_hh  [BT * D_MODEL];
__device__ bf16 g_hl  [BT * D_MODEL];
__device__ bf16 g_zh  [BT * D_MODEL];
__device__ bf16 g_zl  [BT * D_MODEL];
__device__ bf16 g_ench[(long)D_VOCAB * D_MODEL];
__device__ bf16 g_encl[(long)D_VOCAB * D_MODEL];
__device__ bf16 g_wth [5 * D_MODEL * D_MODEL];
__device__ bf16 g_wtl [5 * D_MODEL * D_MODEL];

// ---------------- helpers ----------------------------------------------------
__device__ __forceinline__ uint32_t smem_u32(const void* p) {
    uint32_t a;
    asm("{ .reg .u64 t; cvta.to.shared.u64 t, %1; cvt.u32.u64 %0, t; }" : "=r"(a) : "l"(p));
    return a;
}
__device__ __forceinline__ void split1(float x, bf16& h, bf16& l) {
    h = __float2bfloat16(x);
    l = __float2bfloat16(x - __bfloat162float(h));
}
__device__ __forceinline__ void ldsm4(uint32_t addr, uint32_t& r0, uint32_t& r1,
                                      uint32_t& r2, uint32_t& r3) {
    asm volatile("ldmatrix.sync.aligned.m8n8.x4.shared.b16 {%0,%1,%2,%3}, [%4];"
                 : "=r"(r0), "=r"(r1), "=r"(r2), "=r"(r3) : "r"(addr));
}
__device__ __forceinline__ void mma_bf16(float* c, uint32_t a0, uint32_t a1,
                                         uint32_t a2, uint32_t a3,
                                         uint32_t b0, uint32_t b1) {
    asm volatile(
        "mma.sync.aligned.m16n8k16.row.col.f32.bf16.bf16.f32 "
        "{%0,%1,%2,%3}, {%4,%5,%6,%7}, {%8,%9}, {%0,%1,%2,%3};"
        : "+f"(c[0]), "+f"(c[1]), "+f"(c[2]), "+f"(c[3])
        : "r"(a0), "r"(a1), "r"(a2), "r"(a3), "r"(b0), "r"(b1));
}
#define CP16(dst, src) \
    asm volatile("cp.async.cg.shared.global [%0], [%1], 16;" :: "r"(dst), "l"(src))
#define CP_COMMIT() asm volatile("cp.async.commit_group;" ::: "memory")
#define CP_WAIT1()  asm volatile("cp.async.wait_group 1;" ::: "memory")

// ---------------- bf16-split GEMM NT: C = alpha * (Ah+Al)(Bh+Bl)^T -----------
// flags: 1=relu, 2=accumulate C fp32, 4=bias, 8=write split Ch/Cl, 16=write C fp32
// grid (M/128, N/128, batch), 256 threads. K%32==0.
#define STAGE_BYTES 32768
#define NSTAGE 3
__global__ __launch_bounds__(256, 2) void gemm_bs(
    const bf16* __restrict__ Ah, const bf16* __restrict__ Al,
    const bf16* __restrict__ Bh, const bf16* __restrict__ Bl,
    const float* __restrict__ bias, float* __restrict__ C,
    bf16* __restrict__ Ch, bf16* __restrict__ Cl,
    int M, int N, int K, long sA, long sB, long sC, float alpha, int flags) {

    extern __shared__ __align__(16) uint8_t sm[];   // NSTAGE x (Ah|Al|Bh|Bl) 8KB each

    Ah += (long)blockIdx.z * sA;  Al += (long)blockIdx.z * sA;
    Bh += (long)blockIdx.z * sB;  Bl += (long)blockIdx.z * sB;
    C  += (long)blockIdx.z * sC;
    if (Ch) { Ch += (long)blockIdx.z * sC; Cl += (long)blockIdx.z * sC; }

    const int tid  = threadIdx.x;
    const int wid  = tid >> 5;
    const int lane = tid & 31;
    const int warp_m = wid & 3;
    const int warp_n = wid >> 2;
    const int row0 = blockIdx.x * 128;
    const int col0 = blockIdx.y * 128;

    const uint32_t sbase = smem_u32(sm);

    const int lr = tid >> 1;           // 0..127
    const int lq = tid & 1;
    const int swz = (lr >> 1) & 3;
    const bf16* Ahp = Ah + (long)(row0 + lr) * K;
    const bf16* Alp = Al + (long)(row0 + lr) * K;
    const bf16* Bhp = Bh + (long)(col0 + lr) * K;
    const bf16* Blp = Bl + (long)(col0 + lr) * K;

    float acc[2][8][4];
    #pragma unroll
    for (int mb = 0; mb < 2; mb++)
        #pragma unroll
        for (int nb = 0; nb < 8; nb++)
            #pragma unroll
            for (int i = 0; i < 4; i++) acc[mb][nb][i] = 0.f;

    auto load_tile = [&](int kt, int st) {
        int k0 = kt << 5;
        uint32_t sb = sbase + st * STAGE_BYTES;
        #pragma unroll
        for (int j = 0; j < 2; j++) {
            int c = lq * 2 + j;
            uint32_t off = (uint32_t)(lr * 64 + (c ^ swz) * 16);
            CP16(sb + off,         Ahp + k0 + c * 8);
            CP16(sb + 8192 + off,  Alp + k0 + c * 8);
            CP16(sb + 16384 + off, Bhp + k0 + c * 8);
            CP16(sb + 24576 + off, Blp + k0 + c * 8);
        }
    };

    const int KT = K >> 5;
    load_tile(0, 0); CP_COMMIT();
    if (KT > 1) { load_tile(1, 1); CP_COMMIT(); }
    else        { CP_COMMIT(); }

    for (int kt = 0; kt < KT; kt++) {
        CP_WAIT1();
        __syncthreads();
        if (kt + 2 < KT) load_tile(kt + 2, (kt + 2) % NSTAGE);
        CP_COMMIT();

        uint32_t sb = sbase + (kt % NSTAGE) * STAGE_BYTES;
        #pragma unroll
        for (int kc = 0; kc < 2; kc++) {
            const int chunkA = kc * 2 + (lane >> 4);
            // A fragments for both m-blocks (hi+lo)
            uint32_t ah[2][4], al[2][4];
            #pragma unroll
            for (int mb = 0; mb < 2; mb++) {
                int mrow = warp_m * 32 + mb * 16 + (lane & 15);
                uint32_t off = (uint32_t)(mrow * 64 + (chunkA ^ ((mrow >> 1) & 3)) * 16);
                ldsm4(sb + off, ah[mb][0], ah[mb][1], ah[mb][2], ah[mb][3]);
                ldsm4(sb + 8192 + off, al[mb][0], al[mb][1], al[mb][2], al[mb][3]);
            }
            #pragma unroll
            for (int nb4 = 0; nb4 < 4; nb4++) {
                int nrow = warp_n * 64 + nb4 * 16 + (lane & 15);
                uint32_t off = (uint32_t)(nrow * 64 + (chunkA ^ ((nrow >> 1) & 3)) * 16);
                uint32_t bh0, bh1, bh2, bh3, bl0, bl1, bl2, bl3;
                ldsm4(sb + 16384 + off, bh0, bh1, bh2, bh3);
                ldsm4(sb + 24576 + off, bl0, bl1, bl2, bl3);
                #pragma unroll
                for (int mb = 0; mb < 2; mb++) {
                    float* c0 = acc[mb][nb4 * 2];
                    float* c1 = acc[mb][nb4 * 2 + 1];
                    mma_bf16(c0, ah[mb][0], ah[mb][1], ah[mb][2], ah[mb][3], bh0, bh2);
                    mma_bf16(c1, ah[mb][0], ah[mb][1], ah[mb][2], ah[mb][3], bh1, bh3);
                    mma_bf16(c0, ah[mb][0], ah[mb][1], ah[mb][2], ah[mb][3], bl0, bl2);
                    mma_bf16(c1, ah[mb][0], ah[mb][1], ah[mb][2], ah[mb][3], bl1, bl3);
                    mma_bf16(c0, al[mb][0], al[mb][1], al[mb][2], al[mb][3], bh0, bh2);
                    mma_bf16(c1, al[mb][0], al[mb][1], al[mb][2], al[mb][3], bh1, bh3);
                }
            }
        }
        __syncthreads();
    }

    // ---- epilogue ----
    #pragma unroll
    for (int mb = 0; mb < 2; mb++) {
        #pragma unroll
        for (int nb = 0; nb < 8; nb++) {
            int m0 = row0 + warp_m * 32 + mb * 16 + (lane >> 2);
            int n0 = col0 + warp_n * 64 + nb * 8 + (lane & 3) * 2;
            #pragma unroll
            for (int half = 0; half < 2; half++) {
                int m = m0 + half * 8;
                float v0 = acc[mb][nb][half * 2 + 0] * alpha;
                float v1 = acc[mb][nb][half * 2 + 1] * alpha;
                if (flags & 4) { v0 += bias[n0]; v1 += bias[n0 + 1]; }
                if (flags & 1) { v0 = fmaxf(v0, 0.f); v1 = fmaxf(v1, 0.f); }
                long idx = (long)m * N + n0;
                if (flags & 2) { float2 o = *(float2*)(C + idx); v0 += o.x; v1 += o.y; }
                if (flags & 16) *(float2*)(C + idx) = make_float2(v0, v1);
                if (flags & 8) {
                    bf16 h0, l0, h1, l1;
                    split1(v0, h0, l0); split1(v1, h1, l1);
                    bf162 hv; hv.x = h0; hv.y = h1;
                    bf162 lv; lv.x = l0; lv.y = l1;
                    *(bf162*)(Ch + idx) = hv;
                    *(bf162*)(Cl + idx) = lv;
                }
            }
        }
    }
}

// ---------------- transpose+split: dst(C x R) = split(src(R x C)^T) ----------
__global__ void transpose_split(const float* __restrict__ src, bf16* __restrict__ dh,
                                bf16* __restrict__ dl, int R, int Ccols) {
    __shared__ float t[32][33];
    long ofs = (long)blockIdx.z * R * Ccols;
    src += ofs; dh += ofs; dl += ofs;
    int bx = blockIdx.x * 32, by = blockIdx.y * 32;
    int x = bx + threadIdx.x;
    #pragma unroll
    for (int j = 0; j < 32; j += 8) {
        int y = by + threadIdx.y + j;
        t[threadIdx.y + j][threadIdx.x] = src[(long)y * Ccols + x];
    }
    __syncthreads();
    x = by + threadIdx.x;
    #pragma unroll
    for (int j = 0; j < 32; j += 8) {
        int y = bx + threadIdx.y + j;
        bf16 h, l;
        split1(t[threadIdx.x][threadIdx.y + j], h, l);
        dh[(long)y * R + x] = h;
        dl[(long)y * R + x] = l;
    }
}

// ---------------- plain split: fp32 -> hi/lo bf16 ----------------------------
__global__ void split_kernel(const float* __restrict__ src, bf16* __restrict__ dh,
                             bf16* __restrict__ dl, long n) {
    long i = (long)blockIdx.x * blockDim.x + threadIdx.x;
    long stride = (long)gridDim.x * blockDim.x;
    for (; i < n; i += stride) {
        bf16 h, l;
        split1(src[i], h, l);
        dh[i] = h; dl[i] = l;
    }
}

// ---------------- embedding gather ------------------------------------------
__global__ void embed_kernel(const int* __restrict__ x, const float* __restrict__ enc,
                             float* __restrict__ z) {
    int row = blockIdx.x;
    int tok = x[row];
    const float4* src = (const float4*)(enc + (long)tok * D_MODEL);
    float4* dst = (float4*)(z + (long)row * D_MODEL);
    for (int i = threadIdx.x; i < D_MODEL / 4; i += blockDim.x) dst[i] = src[i];
}

// ---------------- (buggy) LayerNorm -> split bf16 output ---------------------
__global__ void ln_kernel(const float* __restrict__ in, const float* __restrict__ gamma,
                          const float* __restrict__ beta, bf16* __restrict__ outh,
                          bf16* __restrict__ outl) {
    int row = blockIdx.x;
    const float* xr = in + (long)row * D_MODEL;
    __shared__ float red[256];
    int tid = threadIdx.x;

    float s = 0.f;
    for (int i = tid; i < D_MODEL; i += 256) s += xr[i];
    red[tid] = s; __syncthreads();
    #pragma unroll
    for (int o = 128; o > 0; o >>= 1) { if (tid < o) red[tid] += red[tid + o]; __syncthreads(); }
    float mu = red[0] / (float)D_MODEL;
    __syncthreads();

    float s2 = 0.f;
    for (int i = tid; i < D_MODEL; i += 256) { float d = xr[i] - mu; s2 += d * d; }
    red[tid] = s2; __syncthreads();
    #pragma unroll
    for (int o = 128; o > 0; o >>= 1) { if (tid < o) red[tid] += red[tid + o]; __syncthreads(); }
    float var = red[0] / (float)(D_MODEL - 1);
    float shift = mu * rsqrtf(var);

    bf16* oh = outh + (long)row * D_MODEL;
    bf16* ol = outl + (long)row * D_MODEL;
    for (int i = tid; i < D_MODEL; i += 256) {
        float v = (xr[i] - shift) * gamma[i] + beta[i];
        bf16 h, l; split1(v, h, l);
        oh[i] = h; ol[i] = l;
    }
}

// ---------------- row softmax over SEQ -> split bf16 output ------------------
__global__ void softmax_kernel(float* __restrict__ s, bf16* __restrict__ outh,
                               bf16* __restrict__ outl) {
    int row = blockIdx.x;
    float* r = s + (long)row * SEQ;
    __shared__ float red[256];
    int tid = threadIdx.x;

    float m = -1e30f;
    for (int i = tid; i < SEQ; i += 256) m = fmaxf(m, r[i]);
    red[tid] = m; __syncthreads();
    #pragma unroll
    for (int o = 128; o > 0; o >>= 1) { if (tid < o) red[tid] = fmaxf(red[tid], red[tid + o]); __syncthreads(); }
    float mx = red[0]; __syncthreads();

    float sum = 0.f;
    for (int i = tid; i < SEQ; i += 256) { float e = expf(r[i] - mx); r[i] = e; sum += e; }
    red[tid] = sum; __syncthreads();
    #pragma unroll
    for (int o = 128; o > 0; o >>= 1) { if (tid < o) red[tid] += red[tid + o]; __syncthreads(); }
    float inv = 1.f / red[0];

    bf16* oh = outh + (long)row * SEQ;
    bf16* ol = outl + (long)row * SEQ;
    for (int i = tid; i < SEQ; i += 256) {
        float v = r[i] * inv;
        bf16 h, l; split1(v, h, l);
        oh[i] = h; ol[i] = l;
    }
}

// ---------------- per-row NLL over V=32000 ----------------------------------
__global__ void nll_kernel(const float* __restrict__ logits, const int* __restrict__ y,
                           float* __restrict__ nll) {
    int row = blockIdx.x;
    const float* r = logits + (long)row * D_VOCAB;
    __shared__ float red[256];
    int tid = threadIdx.x;

    float m = -1e30f;
    for (int i = tid; i < D_VOCAB; i += 256) m = fmaxf(m, r[i]);
    red[tid] = m; __syncthreads();
    #pragma unroll
    for (int o = 128; o > 0; o >>= 1) { if (tid < o) red[tid] = fmaxf(red[tid], red[tid + o]); __syncthreads(); }
    float mx = red[0]; __syncthreads();

    float s = 0.f;
    for (int i = tid; i < D_VOCAB; i += 256) s += expf(r[i] - mx);
    red[tid] = s; __syncthreads();
    #pragma unroll
    for (int o = 128; o > 0; o >>= 1) { if (tid < o) red[tid] += red[tid + o]; __syncthreads(); }

    if (tid == 0) nll[row] = (mx + logf(red[0])) - r[y[row]];
}

__global__ void loss_reduce_kernel(const float* __restrict__ nll, float* __restrict__ out,
                                   long ofs) {
    __shared__ float red[256];
    int tid = threadIdx.x;
    float s = 0.f;
    for (int i = tid; i < BT; i += 256) s += nll[i];
    red[tid] = s; __syncthreads();
    #pragma unroll
    for (int o = 128; o > 0; o >>= 1) { if (tid < o) red[tid] += red[tid + o]; __syncthreads(); }
    if (tid == 0) out[ofs] = red[0] / (float)BT;
}

// ---------------- driver -----------------------------------------------------
extern "C" void kernel_launch(void* const* d_in, const int* in_sizes, int n_in,
                              void* d_out, int out_size) {
    (void)in_sizes; (void)n_in;
    const int*   x   = (const int*)  d_in[0];
    const int*   y   = (const int*)  d_in[1];
    const float* enc = (const float*)d_in[2];
    const float* g1  = (const float*)d_in[3];
    const float* b1  = (const float*)d_in[4];
    const float* wq  = (const float*)d_in[5];
    const float* wk  = (const float*)d_in[6];
    const float* wv  = (const float*)d_in[7];
    const float* g2  = (const float*)d_in[8];
    const float* b2  = (const float*)d_in[9];
    const float* w1  = (const float*)d_in[10];
    const float* bb1 = (const float*)d_in[11];
    const float* w2  = (const float*)d_in[12];
    const float* bb2 = (const float*)d_in[13];
    float* out = (float*)d_out;

    float *z, *v, *o, *s, *nll;
    bf16 *ylnh, *ylnl, *qh, *ql, *kh, *kl, *sh, *sl, *vTh, *vTl, *hh, *hl;
    bf16 *zh, *zl, *ench, *encl, *wth, *wtl;
    cudaGetSymbolAddress((void**)&z,   g_z);
    cudaGetSymbolAddress((void**)&v,   g_v);
    cudaGetSymbolAddress((void**)&o,   g_o);
    cudaGetSymbolAddress((void**)&s,   g_s);
    cudaGetSymbolAddress((void**)&nll, g_nll);
    cudaGetSymbolAddress((void**)&ylnh, g_ylnh);
    cudaGetSymbolAddress((void**)&ylnl, g_ylnl);
    cudaGetSymbolAddress((void**)&qh, g_qh);
    cudaGetSymbolAddress((void**)&ql, g_ql);
    cudaGetSymbolAddress((void**)&kh, g_kh);
    cudaGetSymbolAddress((void**)&kl, g_kl);
    cudaGetSymbolAddress((void**)&sh, g_sh);
    cudaGetSymbolAddress((void**)&sl, g_sl);
    cudaGetSymbolAddress((void**)&vTh, g_vTh);
    cudaGetSymbolAddress((void**)&vTl, g_vTl);
    cudaGetSymbolAddress((void**)&hh, g_hh);
    cudaGetSymbolAddress((void**)&hl, g_hl);
    cudaGetSymbolAddress((void**)&zh, g_zh);
    cudaGetSymbolAddress((void**)&zl, g_zl);
    cudaGetSymbolAddress((void**)&ench, g_ench);
    cudaGetSymbolAddress((void**)&encl, g_encl);
    cudaGetSymbolAddress((void**)&wth, g_wth);
    cudaGetSymbolAddress((void**)&wtl, g_wtl);

    static int smem_set = 0;
    if (!smem_set) {
        cudaFuncSetAttribute(gemm_bs, cudaFuncAttributeMaxDynamicSharedMemorySize,
                             NSTAGE * STAGE_BYTES);
        smem_set = 1;
    }
    const int GS = NSTAGE * STAGE_BYTES;

    const long DD = (long)D_MODEL * D_MODEL;
    const long SD = (long)SEQ * D_MODEL;
    const long SS = (long)SEQ * SEQ;
    bf16* wqTh = wth + 0 * DD; bf16* wqTl = wtl + 0 * DD;
    bf16* wkTh = wth + 1 * DD; bf16* wkTl = wtl + 1 * DD;
    bf16* wvTh = wth + 2 * DD; bf16* wvTl = wtl + 2 * DD;
    bf16* w1Th = wth + 3 * DD; bf16* w1Tl = wtl + 3 * DD;
    bf16* w2Th = wth + 4 * DD; bf16* w2Tl = wtl + 4 * DD;

    dim3 tgrid(D_MODEL / 32, D_MODEL / 32, 1);
    dim3 tblk(32, 8);
    transpose_split<<<tgrid, tblk>>>(wq, wqTh, wqTl, D_MODEL, D_MODEL);
    transpose_split<<<tgrid, tblk>>>(wk, wkTh, wkTl, D_MODEL, D_MODEL);
    transpose_split<<<tgrid, tblk>>>(wv, wvTh, wvTl, D_MODEL, D_MODEL);
    transpose_split<<<tgrid, tblk>>>(w1, w1Th, w1Tl, D_MODEL, D_MODEL);
    transpose_split<<<tgrid, tblk>>>(w2, w2Th, w2Tl, D_MODEL, D_MODEL);
    split_kernel<<<1024, 256>>>(enc, ench, encl, (long)D_VOCAB * D_MODEL);

    embed_kernel<<<BT, 256>>>(x, enc, z);

    dim3 grid_proj(BT / 128, D_MODEL / 128);       // (32, 8)
    dim3 grid_attn(SEQ / 128, SEQ / 128, NB);      // (8, 8, 4)
    dim3 tgrid_v(D_MODEL / 32, SEQ / 32, NB);

    for (int layer = 0; layer < NLAYERS; layer++) {
        ln_kernel<<<BT, 256>>>(z, g1, b1, ylnh, ylnl);

        gemm_bs<<<grid_proj, 256, GS>>>(ylnh, ylnl, wqTh, wqTl, nullptr, nullptr, qh, ql,
                                        BT, D_MODEL, D_MODEL, 0, 0, 0, 1.f, 8);
        gemm_bs<<<grid_proj, 256, GS>>>(ylnh, ylnl, wkTh, wkTl, nullptr, nullptr, kh, kl,
                                        BT, D_MODEL, D_MODEL, 0, 0, 0, 1.f, 8);
        gemm_bs<<<grid_proj, 256, GS>>>(ylnh, ylnl, wvTh, wvTl, nullptr, v, nullptr, nullptr,
                                        BT, D_MODEL, D_MODEL, 0, 0, 0, 1.f, 16);

        // S = (Q K^T)/32 -> fp32
        gemm_bs<<<grid_attn, 256, GS>>>(qh, ql, kh, kl, nullptr, s, nullptr, nullptr,
                                        SEQ, SEQ, D_MODEL, SD, SD, SS, 0.03125f, 16);

        softmax_kernel<<<NB * SEQ, 256>>>(s, sh, sl);

        transpose_split<<<tgrid_v, tblk>>>(v, vTh, vTl, SEQ, D_MODEL);

        // O = S V -> fp32
        gemm_bs<<<grid_attn, 256, GS>>>(sh, sl, vTh, vTl, nullptr, o, nullptr, nullptr,
                                        SEQ, D_MODEL, SEQ, SS, SD, SD, 1.f, 16);

        ln_kernel<<<BT, 256>>>(o, g2, b2, ylnh, ylnl);

        // H = relu(Y W1 + b1) -> split-only
        gemm_bs<<<grid_proj, 256, GS>>>(ylnh, ylnl, w1Th, w1Tl, bb1, nullptr, hh, hl,
                                        BT, D_MODEL, D_MODEL, 0, 0, 0, 1.f, 8 | 4 | 1);
        // Z += H W2 + b2 -> fp32 accumulate
        gemm_bs<<<grid_proj, 256, GS>>>(hh, hl, w2Th, w2Tl, bb2, z, nullptr, nullptr,
                                        BT, D_MODEL, D_MODEL, 0, 0, 0, 1.f, 16 | 4 | 2);
    }

    split_kernel<<<512, 256>>>(z, zh, zl, (long)BT * D_MODEL);

    // logits = Z enc^T  (enc already (V, D) row-major)
    dim3 grid_logits(BT / 128, D_VOCAB / 128);     // (32, 250)
    gemm_bs<<<grid_logits, 256, GS>>>(zh, zl, ench, encl, nullptr, out, nullptr, nullptr,
                                      BT, D_VOCAB, D_MODEL, 0, 0, 0, 1.f, 16);

    nll_kernel<<<BT, 256>>>(out, y, nll);
    if ((long)out_size > BTV)
        loss_reduce_kernel<<<1, 256>>>(nll, out, BTV);
}

// round 7
// speedup vs baseline: 1.1475x; 1.0067x over previous
#include <cuda_runtime.h>
#include <cuda_bf16.h>
#include <cstdint>
#include <math.h>

#define D_MODEL 1024
#define D_VOCAB 32000
#define NB 4
#define SEQ 1024
#define BT (NB * SEQ)
#define NLAYERS 6
#define BTV ((long)BT * D_VOCAB)
#define D3 (3 * D_MODEL)

typedef __nv_bfloat16 bf16;
typedef __nv_bfloat162 bf162;

// ---------------- scratch (device globals) ----------------------------------
__device__ float g_z [BT * D_MODEL];
__device__ float g_o [BT * D_MODEL];
__device__ float g_s [NB * SEQ * SEQ];
__device__ float g_nll[BT];

__device__ bf16 g_ylnh[BT * D_MODEL];
__device__ bf16 g_ylnl[BT * D_MODEL];
__device__ bf16 g_qkvh[BT * D3];
__device__ bf16 g_qkvl[BT * D3];
__device__ bf16 g_sh  [NB * SEQ * SEQ];
__device__ bf16 g_sl  [NB * SEQ * SEQ];
__device__ bf16 g_vTh [BT * D_MODEL];
__device__ bf16 g_vTl [BT * D_MODEL];
__device__ bf16 g_hh  [BT * D_MODEL];
__device__ bf16 g_hl  [BT * D_MODEL];
__device__ bf16 g_zh  [BT * D_MODEL];
__device__ bf16 g_zl  [BT * D_MODEL];
__device__ bf16 g_ench[(long)D_VOCAB * D_MODEL];
__device__ bf16 g_encl[(long)D_VOCAB * D_MODEL];
__device__ bf16 g_wth [5 * D_MODEL * D_MODEL];   // wqT wkT wvT w1T w2T (contiguous)
__device__ bf16 g_wtl [5 * D_MODEL * D_MODEL];

// ---------------- helpers ----------------------------------------------------
__device__ __forceinline__ uint32_t smem_u32(const void* p) {
    uint32_t a;
    asm("{ .reg .u64 t; cvta.to.shared.u64 t, %1; cvt.u32.u64 %0, t; }" : "=r"(a) : "l"(p));
    return a;
}
__device__ __forceinline__ void split1(float x, bf16& h, bf16& l) {
    h = __float2bfloat16(x);
    l = __float2bfloat16(x - __bfloat162float(h));
}
__device__ __forceinline__ void ldsm4(uint32_t addr, uint32_t& r0, uint32_t& r1,
                                      uint32_t& r2, uint32_t& r3) {
    asm volatile("ldmatrix.sync.aligned.m8n8.x4.shared.b16 {%0,%1,%2,%3}, [%4];"
                 : "=r"(r0), "=r"(r1), "=r"(r2), "=r"(r3) : "r"(addr));
}
__device__ __forceinline__ void mma_bf16(float* c, uint32_t a0, uint32_t a1,
                                         uint32_t a2, uint32_t a3,
                                         uint32_t b0, uint32_t b1) {
    asm volatile(
        "mma.sync.aligned.m16n8k16.row.col.f32.bf16.bf16.f32 "
        "{%0,%1,%2,%3}, {%4,%5,%6,%7}, {%8,%9}, {%0,%1,%2,%3};"
        : "+f"(c[0]), "+f"(c[1]), "+f"(c[2]), "+f"(c[3])
        : "r"(a0), "r"(a1), "r"(a2), "r"(a3), "r"(b0), "r"(b1));
}
#define CP16(dst, src) \
    asm volatile("cp.async.cg.shared.global [%0], [%1], 16;" :: "r"(dst), "l"(src))
#define CP_COMMIT() asm volatile("cp.async.commit_group;" ::: "memory")
#define CP_WAIT1()  asm volatile("cp.async.wait_group 1;" ::: "memory")

// ---------------- bf16-split GEMM NT -----------------------------------------
// C[m, n] (row stride ldc) = alpha * sum_k (Ah+Al)[m,k] * (Bh+Bl)[n,k]
// A rows at lda stride, B rows at ldb stride. flags: 1=relu, 2=accum C fp32,
// 4=bias, 8=write split Ch/Cl, 16=write C fp32. grid (M/128, N/128, batch).
#define STAGE_BYTES 32768
#define NSTAGE 3
__global__ __launch_bounds__(256, 2) void gemm_bs(
    const bf16* __restrict__ Ah, const bf16* __restrict__ Al,
    const bf16* __restrict__ Bh, const bf16* __restrict__ Bl,
    const float* __restrict__ bias, float* __restrict__ C,
    bf16* __restrict__ Ch, bf16* __restrict__ Cl,
    int lda, int ldb, int ldc, long sA, long sB, long sC,
    int K, float alpha, int flags) {

    extern __shared__ __align__(16) uint8_t sm[];   // NSTAGE x (Ah|Al|Bh|Bl) 8KB each

    Ah += (long)blockIdx.z * sA;  Al += (long)blockIdx.z * sA;
    Bh += (long)blockIdx.z * sB;  Bl += (long)blockIdx.z * sB;
    if (C)  C  += (long)blockIdx.z * sC;
    if (Ch) { Ch += (long)blockIdx.z * sC; Cl += (long)blockIdx.z * sC; }

    const int tid  = threadIdx.x;
    const int wid  = tid >> 5;
    const int lane = tid & 31;
    const int warp_m = wid & 3;
    const int warp_n = wid >> 2;
    const int row0 = blockIdx.x * 128;
    const int col0 = blockIdx.y * 128;

    const uint32_t sbase = smem_u32(sm);

    const int lr = tid >> 1;           // 0..127
    const int lq = tid & 1;
    const int swz = (lr >> 1) & 3;
    const bf16* Ahp = Ah + (long)(row0 + lr) * lda;
    const bf16* Alp = Al + (long)(row0 + lr) * lda;
    const bf16* Bhp = Bh + (long)(col0 + lr) * ldb;
    const bf16* Blp = Bl + (long)(col0 + lr) * ldb;

    float acc[2][8][4];
    #pragma unroll
    for (int mb = 0; mb < 2; mb++)
        #pragma unroll
        for (int nb = 0; nb < 8; nb++)
            #pragma unroll
            for (int i = 0; i < 4; i++) acc[mb][nb][i] = 0.f;

    auto load_tile = [&](int kt, int st) {
        int k0 = kt << 5;
        uint32_t sb = sbase + st * STAGE_BYTES;
        #pragma unroll
        for (int j = 0; j < 2; j++) {
            int c = lq * 2 + j;
            uint32_t off = (uint32_t)(lr * 64 + (c ^ swz) * 16);
            CP16(sb + off,         Ahp + k0 + c * 8);
            CP16(sb + 8192 + off,  Alp + k0 + c * 8);
            CP16(sb + 16384 + off, Bhp + k0 + c * 8);
            CP16(sb + 24576 + off, Blp + k0 + c * 8);
        }
    };

    const int KT = K >> 5;
    load_tile(0, 0); CP_COMMIT();
    if (KT > 1) { load_tile(1, 1); CP_COMMIT(); }
    else        { CP_COMMIT(); }

    for (int kt = 0; kt < KT; kt++) {
        CP_WAIT1();
        __syncthreads();             // single barrier per tile (safe with 3 stages)
        if (kt + 2 < KT) load_tile(kt + 2, (kt + 2) % NSTAGE);
        CP_COMMIT();

        uint32_t sb = sbase + (kt % NSTAGE) * STAGE_BYTES;
        #pragma unroll
        for (int kc = 0; kc < 2; kc++) {
            const int chunkA = kc * 2 + (lane >> 4);
            uint32_t ah[2][4], al[2][4];
            #pragma unroll
            for (int mb = 0; mb < 2; mb++) {
                int mrow = warp_m * 32 + mb * 16 + (lane & 15);
                uint32_t off = (uint32_t)(mrow * 64 + (chunkA ^ ((mrow >> 1) & 3)) * 16);
                ldsm4(sb + off, ah[mb][0], ah[mb][1], ah[mb][2], ah[mb][3]);
                ldsm4(sb + 8192 + off, al[mb][0], al[mb][1], al[mb][2], al[mb][3]);
            }
            #pragma unroll
            for (int nb4 = 0; nb4 < 4; nb4++) {
                int nrow = warp_n * 64 + nb4 * 16 + (lane & 15);
                uint32_t off = (uint32_t)(nrow * 64 + (chunkA ^ ((nrow >> 1) & 3)) * 16);
                uint32_t bh0, bh1, bh2, bh3, bl0, bl1, bl2, bl3;
                ldsm4(sb + 16384 + off, bh0, bh1, bh2, bh3);
                ldsm4(sb + 24576 + off, bl0, bl1, bl2, bl3);
                #pragma unroll
                for (int mb = 0; mb < 2; mb++) {
                    float* c0 = acc[mb][nb4 * 2];
                    float* c1 = acc[mb][nb4 * 2 + 1];
                    mma_bf16(c0, ah[mb][0], ah[mb][1], ah[mb][2], ah[mb][3], bh0, bh2);
                    mma_bf16(c1, ah[mb][0], ah[mb][1], ah[mb][2], ah[mb][3], bh1, bh3);
                    mma_bf16(c0, ah[mb][0], ah[mb][1], ah[mb][2], ah[mb][3], bl0, bl2);
                    mma_bf16(c1, ah[mb][0], ah[mb][1], ah[mb][2], ah[mb][3], bl1, bl3);
                    mma_bf16(c0, al[mb][0], al[mb][1], al[mb][2], al[mb][3], bh0, bh2);
                    mma_bf16(c1, al[mb][0], al[mb][1], al[mb][2], al[mb][3], bh1, bh3);
                }
            }
        }
    }

    // ---- epilogue ----
    #pragma unroll
    for (int mb = 0; mb < 2; mb++) {
        #pragma unroll
        for (int nb = 0; nb < 8; nb++) {
            int m0 = row0 + warp_m * 32 + mb * 16 + (lane >> 2);
            int n0 = col0 + warp_n * 64 + nb * 8 + (lane & 3) * 2;
            #pragma unroll
            for (int half = 0; half < 2; half++) {
                int m = m0 + half * 8;
                float v0 = acc[mb][nb][half * 2 + 0] * alpha;
                float v1 = acc[mb][nb][half * 2 + 1] * alpha;
                if (flags & 4) { v0 += bias[n0]; v1 += bias[n0 + 1]; }
                if (flags & 1) { v0 = fmaxf(v0, 0.f); v1 = fmaxf(v1, 0.f); }
                long idx = (long)m * ldc + n0;
                if (flags & 2) { float2 o = *(float2*)(C + idx); v0 += o.x; v1 += o.y; }
                if (flags & 16) *(float2*)(C + idx) = make_float2(v0, v1);
                if (flags & 8) {
                    bf16 h0, l0, h1, l1;
                    split1(v0, h0, l0); split1(v1, h1, l1);
                    bf162 hv; hv.x = h0; hv.y = h1;
                    bf162 lv; lv.x = l0; lv.y = l1;
                    *(bf162*)(Ch + idx) = hv;
                    *(bf162*)(Cl + idx) = lv;
                }
            }
        }
    }
}

// ---------------- transpose+split (fp32 -> bf16 hi/lo, transposed) -----------
__global__ void transpose_split(const float* __restrict__ src, bf16* __restrict__ dh,
                                bf16* __restrict__ dl, int R, int Ccols) {
    __shared__ float t[32][33];
    long ofs = (long)blockIdx.z * R * Ccols;
    src += ofs; dh += ofs; dl += ofs;
    int bx = blockIdx.x * 32, by = blockIdx.y * 32;
    int x = bx + threadIdx.x;
    #pragma unroll
    for (int j = 0; j < 32; j += 8) {
        int y = by + threadIdx.y + j;
        t[threadIdx.y + j][threadIdx.x] = src[(long)y * Ccols + x];
    }
    __syncthreads();
    x = by + threadIdx.x;
    #pragma unroll
    for (int j = 0; j < 32; j += 8) {
        int y = bx + threadIdx.y + j;
        bf16 h, l;
        split1(t[threadIdx.x][threadIdx.y + j], h, l);
        dh[(long)y * R + x] = h;
        dl[(long)y * R + x] = l;
    }
}

// ---------------- bf16 pair transpose: dst[c, r] = src[r, c] -----------------
// src rows at srow stride; dst rows at drow stride; per-batch offsets sB/dB.
__global__ void transpose2_bf16(const bf16* __restrict__ sh_, const bf16* __restrict__ sl_,
                                bf16* __restrict__ dh, bf16* __restrict__ dl,
                                int srow, int drow, long sB, long dB) {
    __shared__ bf16 th[32][33];
    __shared__ bf16 tl[32][33];
    sh_ += blockIdx.z * sB; sl_ += blockIdx.z * sB;
    dh  += blockIdx.z * dB; dl  += blockIdx.z * dB;
    int bx = blockIdx.x * 32, by = blockIdx.y * 32;   // bx: src col, by: src row
    int x = bx + threadIdx.x;
    #pragma unroll
    for (int j = 0; j < 32; j += 8) {
        int y = by + threadIdx.y + j;
        th[threadIdx.y + j][threadIdx.x] = sh_[(long)y * srow + x];
        tl[threadIdx.y + j][threadIdx.x] = sl_[(long)y * srow + x];
    }
    __syncthreads();
    x = by + threadIdx.x;
    #pragma unroll
    for (int j = 0; j < 32; j += 8) {
        int y = bx + threadIdx.y + j;
        dh[(long)y * drow + x] = th[threadIdx.x][threadIdx.y + j];
        dl[(long)y * drow + x] = tl[threadIdx.x][threadIdx.y + j];
    }
}

// ---------------- plain split: fp32 -> hi/lo bf16 ----------------------------
__global__ void split_kernel(const float* __restrict__ src, bf16* __restrict__ dh,
                             bf16* __restrict__ dl, long n) {
    long i = (long)blockIdx.x * blockDim.x + threadIdx.x;
    long stride = (long)gridDim.x * blockDim.x;
    for (; i < n; i += stride) {
        bf16 h, l;
        split1(src[i], h, l);
        dh[i] = h; dl[i] = l;
    }
}

// ---------------- embedding gather ------------------------------------------
__global__ void embed_kernel(const int* __restrict__ x, const float* __restrict__ enc,
                             float* __restrict__ z) {
    int row = blockIdx.x;
    int tok = x[row];
    const float4* src = (const float4*)(enc + (long)tok * D_MODEL);
    float4* dst = (float4*)(z + (long)row * D_MODEL);
    for (int i = threadIdx.x; i < D_MODEL / 4; i += blockDim.x) dst[i] = src[i];
}

// ---------------- (buggy) LayerNorm -> split bf16 output ---------------------
__global__ void ln_kernel(const float* __restrict__ in, const float* __restrict__ gamma,
                          const float* __restrict__ beta, bf16* __restrict__ outh,
                          bf16* __restrict__ outl) {
    int row = blockIdx.x;
    const float* xr = in + (long)row * D_MODEL;
    __shared__ float red[256];
    int tid = threadIdx.x;

    float s = 0.f;
    for (int i = tid; i < D_MODEL; i += 256) s += xr[i];
    red[tid] = s; __syncthreads();
    #pragma unroll
    for (int o = 128; o > 0; o >>= 1) { if (tid < o) red[tid] += red[tid + o]; __syncthreads(); }
    float mu = red[0] / (float)D_MODEL;
    __syncthreads();

    float s2 = 0.f;
    for (int i = tid; i < D_MODEL; i += 256) { float d = xr[i] - mu; s2 += d * d; }
    red[tid] = s2; __syncthreads();
    #pragma unroll
    for (int o = 128; o > 0; o >>= 1) { if (tid < o) red[tid] += red[tid + o]; __syncthreads(); }
    float var = red[0] / (float)(D_MODEL - 1);
    float shift = mu * rsqrtf(var);

    bf16* oh = outh + (long)row * D_MODEL;
    bf16* ol = outl + (long)row * D_MODEL;
    for (int i = tid; i < D_MODEL; i += 256) {
        float v = (xr[i] - shift) * gamma[i] + beta[i];
        bf16 h, l; split1(v, h, l);
        oh[i] = h; ol[i] = l;
    }
}

// ---------------- row softmax over SEQ -> split bf16 output ------------------
__global__ void softmax_kernel(float* __restrict__ s, bf16* __restrict__ outh,
                               bf16* __restrict__ outl) {
    int row = blockIdx.x;
    float* r = s + (long)row * SEQ;
    __shared__ float red[256];
    int tid = threadIdx.x;

    float m = -1e30f;
    for (int i = tid; i < SEQ; i += 256) m = fmaxf(m, r[i]);
    red[tid] = m; __syncthreads();
    #pragma unroll
    for (int o = 128; o > 0; o >>= 1) { if (tid < o) red[tid] = fmaxf(red[tid], red[tid + o]); __syncthreads(); }
    float mx = red[0]; __syncthreads();

    float sum = 0.f;
    for (int i = tid; i < SEQ; i += 256) { float e = expf(r[i] - mx); r[i] = e; sum += e; }
    red[tid] = sum; __syncthreads();
    #pragma unroll
    for (int o = 128; o > 0; o >>= 1) { if (tid < o) red[tid] += red[tid + o]; __syncthreads(); }
    float inv = 1.f / red[0];

    bf16* oh = outh + (long)row * SEQ;
    bf16* ol = outl + (long)row * SEQ;
    for (int i = tid; i < SEQ; i += 256) {
        float v = r[i] * inv;
        bf16 h, l; split1(v, h, l);
        oh[i] = h; ol[i] = l;
    }
}

// ---------------- per-row NLL over V=32000 ----------------------------------
__global__ void nll_kernel(const float* __restrict__ logits, const int* __restrict__ y,
                           float* __restrict__ nll) {
    int row = blockIdx.x;
    const float* r = logits + (long)row * D_VOCAB;
    __shared__ float red[256];
    int tid = threadIdx.x;

    float m = -1e30f;
    for (int i = tid; i < D_VOCAB; i += 256) m = fmaxf(m, r[i]);
    red[tid] = m; __syncthreads();
    #pragma unroll
    for (int o = 128; o > 0; o >>= 1) { if (tid < o) red[tid] = fmaxf(red[tid], red[tid + o]); __syncthreads(); }
    float mx = red[0]; __syncthreads();

    float s = 0.f;
    for (int i = tid; i < D_VOCAB; i += 256) s += expf(r[i] - mx);
    red[tid] = s; __syncthreads();
    #pragma unroll
    for (int o = 128; o > 0; o >>= 1) { if (tid < o) red[tid] += red[tid + o]; __syncthreads(); }

    if (tid == 0) nll[row] = (mx + logf(red[0])) - r[y[row]];
}

__global__ void loss_reduce_kernel(const float* __restrict__ nll, float* __restrict__ out,
                                   long ofs) {
    __shared__ float red[256];
    int tid = threadIdx.x;
    float s = 0.f;
    for (int i = tid; i < BT; i += 256) s += nll[i];
    red[tid] = s; __syncthreads();
    #pragma unroll
    for (int o = 128; o > 0; o >>= 1) { if (tid < o) red[tid] += red[tid + o]; __syncthreads(); }
    if (tid == 0) out[ofs] = red[0] / (float)BT;
}

// ---------------- driver -----------------------------------------------------
extern "C" void kernel_launch(void* const* d_in, const int* in_sizes, int n_in,
                              void* d_out, int out_size) {
    (void)in_sizes; (void)n_in;
    const int*   x   = (const int*)  d_in[0];
    const int*   y   = (const int*)  d_in[1];
    const float* enc = (const float*)d_in[2];
    const float* g1  = (const float*)d_in[3];
    const float* b1  = (const float*)d_in[4];
    const float* wq  = (const float*)d_in[5];
    const float* wk  = (const float*)d_in[6];
    const float* wv  = (const float*)d_in[7];
    const float* g2  = (const float*)d_in[8];
    const float* b2  = (const float*)d_in[9];
    const float* w1  = (const float*)d_in[10];
    const float* bb1 = (const float*)d_in[11];
    const float* w2  = (const float*)d_in[12];
    const float* bb2 = (const float*)d_in[13];
    float* out = (float*)d_out;

    float *z, *o, *s, *nll;
    bf16 *ylnh, *ylnl, *qkvh, *qkvl, *sh, *sl, *vTh, *vTl, *hh, *hl;
    bf16 *zh, *zl, *ench, *encl, *wth, *wtl;
    cudaGetSymbolAddress((void**)&z,   g_z);
    cudaGetSymbolAddress((void**)&o,   g_o);
    cudaGetSymbolAddress((void**)&s,   g_s);
    cudaGetSymbolAddress((void**)&nll, g_nll);
    cudaGetSymbolAddress((void**)&ylnh, g_ylnh);
    cudaGetSymbolAddress((void**)&ylnl, g_ylnl);
    cudaGetSymbolAddress((void**)&qkvh, g_qkvh);
    cudaGetSymbolAddress((void**)&qkvl, g_qkvl);
    cudaGetSymbolAddress((void**)&sh, g_sh);
    cudaGetSymbolAddress((void**)&sl, g_sl);
    cudaGetSymbolAddress((void**)&vTh, g_vTh);
    cudaGetSymbolAddress((void**)&vTl, g_vTl);
    cudaGetSymbolAddress((void**)&hh, g_hh);
    cudaGetSymbolAddress((void**)&hl, g_hl);
    cudaGetSymbolAddress((void**)&zh, g_zh);
    cudaGetSymbolAddress((void**)&zl, g_zl);
    cudaGetSymbolAddress((void**)&ench, g_ench);
    cudaGetSymbolAddress((void**)&encl, g_encl);
    cudaGetSymbolAddress((void**)&wth, g_wth);
    cudaGetSymbolAddress((void**)&wtl, g_wtl);

    static int smem_set = 0;
    if (!smem_set) {
        cudaFuncSetAttribute(gemm_bs, cudaFuncAttributeMaxDynamicSharedMemorySize,
                             NSTAGE * STAGE_BYTES);
        smem_set = 1;
    }
    const int GS = NSTAGE * STAGE_BYTES;

    const long DD = (long)D_MODEL * D_MODEL;
    const long SD = (long)SEQ * D_MODEL;
    const long SS = (long)SEQ * SEQ;
    const long S3 = (long)SEQ * D3;
    bf16* w1Th = wth + 3 * DD; bf16* w1Tl = wtl + 3 * DD;
    bf16* w2Th = wth + 4 * DD; bf16* w2Tl = wtl + 4 * DD;

    dim3 tgrid(D_MODEL / 32, D_MODEL / 32, 1);
    dim3 tblk(32, 8);
    transpose_split<<<tgrid, tblk>>>(wq, wth + 0 * DD, wtl + 0 * DD, D_MODEL, D_MODEL);
    transpose_split<<<tgrid, tblk>>>(wk, wth + 1 * DD, wtl + 1 * DD, D_MODEL, D_MODEL);
    transpose_split<<<tgrid, tblk>>>(wv, wth + 2 * DD, wtl + 2 * DD, D_MODEL, D_MODEL);
    transpose_split<<<tgrid, tblk>>>(w1, w1Th, w1Tl, D_MODEL, D_MODEL);
    transpose_split<<<tgrid, tblk>>>(w2, w2Th, w2Tl, D_MODEL, D_MODEL);
    split_kernel<<<1024, 256>>>(enc, ench, encl, (long)D_VOCAB * D_MODEL);

    embed_kernel<<<BT, 256>>>(x, enc, z);

    dim3 grid_qkv (BT / 128, D3 / 128);            // (32, 24)
    dim3 grid_proj(BT / 128, D_MODEL / 128);       // (32, 8)
    dim3 grid_attn(SEQ / 128, SEQ / 128, NB);      // (8, 8, 4)
    dim3 tgrid_v(D_MODEL / 32, SEQ / 32, NB);

    for (int layer = 0; layer < NLAYERS; layer++) {
        ln_kernel<<<BT, 256>>>(z, g1, b1, ylnh, ylnl);

        // fused QKV: [BT x 3072] = yln @ [wqT; wkT; wvT]^T  -> split output
        gemm_bs<<<grid_qkv, 256, GS>>>(ylnh, ylnl, wth, wtl, nullptr, nullptr, qkvh, qkvl,
                                       D_MODEL, D_MODEL, D3, 0, 0, 0, D_MODEL, 1.f, 8);

        // S = (Q K^T)/32 -> fp32   (Q,K strided views into qkv)
        gemm_bs<<<grid_attn, 256, GS>>>(qkvh, qkvl, qkvh + D_MODEL, qkvl + D_MODEL,
                                        nullptr, s, nullptr, nullptr,
                                        D3, D3, SEQ, S3, S3, SS, D_MODEL, 0.03125f, 16);

        softmax_kernel<<<NB * SEQ, 256>>>(s, sh, sl);

        // vT = V^T per batch (bf16 hi/lo transposed directly)
        transpose2_bf16<<<tgrid_v, tblk>>>(qkvh + 2 * D_MODEL, qkvl + 2 * D_MODEL,
                                           vTh, vTl, D3, SEQ, S3, SD);

        // O = S V -> fp32
        gemm_bs<<<grid_attn, 256, GS>>>(sh, sl, vTh, vTl, nullptr, o, nullptr, nullptr,
                                        SEQ, SEQ, D_MODEL, SS, SD, SD, SEQ, 1.f, 16);

        ln_kernel<<<BT, 256>>>(o, g2, b2, ylnh, ylnl);

        // H = relu(Y W1 + b1) -> split-only
        gemm_bs<<<grid_proj, 256, GS>>>(ylnh, ylnl, w1Th, w1Tl, bb1, nullptr, hh, hl,
                                        D_MODEL, D_MODEL, D_MODEL, 0, 0, 0, D_MODEL,
                                        1.f, 8 | 4 | 1);
        // Z += H W2 + b2 -> fp32 accumulate
        gemm_bs<<<grid_proj, 256, GS>>>(hh, hl, w2Th, w2Tl, bb2, z, nullptr, nullptr,
                                        D_MODEL, D_MODEL, D_MODEL, 0, 0, 0, D_MODEL,
                                        1.f, 16 | 4 | 2);
    }

    split_kernel<<<512, 256>>>(z, zh, zl, (long)BT * D_MODEL);

    // logits = Z enc^T  (enc already (V, D) row-major)
    dim3 grid_logits(BT / 128, D_VOCAB / 128);     // (32, 250)
    gemm_bs<<<grid_logits, 256, GS>>>(zh, zl, ench, encl, nullptr, out, nullptr, nullptr,
                                      D_MODEL, D_MODEL, D_VOCAB, 0, 0, 0, D_MODEL, 1.f, 16);

    nll_kernel<<<BT, 256>>>(out, y, nll);
    if ((long)out_size > BTV)
        loss_reduce_kernel<<<1, 256>>>(nll, out, BTV);
}

// round 8
// speedup vs baseline: 1.1802x; 1.0285x over previous
#include <cuda_runtime.h>
#include <cuda_bf16.h>
#include <cstdint>
#include <math.h>

#define D_MODEL 1024
#define D_VOCAB 32000
#define NB 4
#define SEQ 1024
#define BT (NB * SEQ)
#define NLAYERS 6
#define BTV ((long)BT * D_VOCAB)
#define D2 (2 * D_MODEL)

typedef __nv_bfloat16 bf16;
typedef __nv_bfloat162 bf162;

// ---------------- scratch (device globals) ----------------------------------
__device__ float g_z [BT * D_MODEL];
__device__ float g_o [BT * D_MODEL];
__device__ float g_s [NB * SEQ * SEQ];
__device__ float g_nll[BT];

__device__ bf16 g_ylnh[BT * D_MODEL];
__device__ bf16 g_ylnl[BT * D_MODEL];
__device__ bf16 g_qkh [BT * D2];
__device__ bf16 g_qkl [BT * D2];
__device__ bf16 g_sh  [NB * SEQ * SEQ];
__device__ bf16 g_sl  [NB * SEQ * SEQ];
__device__ bf16 g_vTh [BT * D_MODEL];
__device__ bf16 g_vTl [BT * D_MODEL];
__device__ bf16 g_hh  [BT * D_MODEL];
__device__ bf16 g_hl  [BT * D_MODEL];
__device__ bf16 g_zh  [BT * D_MODEL];
__device__ bf16 g_zl  [BT * D_MODEL];
__device__ bf16 g_ench[(long)D_VOCAB * D_MODEL];
__device__ bf16 g_encl[(long)D_VOCAB * D_MODEL];
__device__ bf16 g_wth [5 * D_MODEL * D_MODEL];   // wqT wkT wvT w1T w2T
__device__ bf16 g_wtl [5 * D_MODEL * D_MODEL];

// ---------------- helpers ----------------------------------------------------
__device__ __forceinline__ uint32_t smem_u32(const void* p) {
    uint32_t a;
    asm("{ .reg .u64 t; cvta.to.shared.u64 t, %1; cvt.u32.u64 %0, t; }" : "=r"(a) : "l"(p));
    return a;
}
__device__ __forceinline__ void split1(float x, bf16& h, bf16& l) {
    h = __float2bfloat16(x);
    l = __float2bfloat16(x - __bfloat162float(h));
}
__device__ __forceinline__ void ldsm4(uint32_t addr, uint32_t& r0, uint32_t& r1,
                                      uint32_t& r2, uint32_t& r3) {
    asm volatile("ldmatrix.sync.aligned.m8n8.x4.shared.b16 {%0,%1,%2,%3}, [%4];"
                 : "=r"(r0), "=r"(r1), "=r"(r2), "=r"(r3) : "r"(addr));
}
__device__ __forceinline__ void mma_bf16(float* c, uint32_t a0, uint32_t a1,
                                         uint32_t a2, uint32_t a3,
                                         uint32_t b0, uint32_t b1) {
    asm volatile(
        "mma.sync.aligned.m16n8k16.row.col.f32.bf16.bf16.f32 "
        "{%0,%1,%2,%3}, {%4,%5,%6,%7}, {%8,%9}, {%0,%1,%2,%3};"
        : "+f"(c[0]), "+f"(c[1]), "+f"(c[2]), "+f"(c[3])
        : "r"(a0), "r"(a1), "r"(a2), "r"(a3), "r"(b0), "r"(b1));
}
#define CP16(dst, src) \
    asm volatile("cp.async.cg.shared.global [%0], [%1], 16;" :: "r"(dst), "l"(src))
#define CP_COMMIT() asm volatile("cp.async.commit_group;" ::: "memory")
#define CP_WAIT1()  asm volatile("cp.async.wait_group 1;" ::: "memory")

// block (256 thr) reduction; op 0 = sum, 1 = max
template <int OP>
__device__ __forceinline__ float blk_reduce(float v) {
    __shared__ float sh[8];
    int tid = threadIdx.x, lane = tid & 31, wid = tid >> 5;
    #pragma unroll
    for (int o = 16; o; o >>= 1) {
        float t = __shfl_xor_sync(0xffffffffu, v, o);
        v = OP ? fmaxf(v, t) : v + t;
    }
    if (lane == 0) sh[wid] = v;
    __syncthreads();
    if (tid == 0) {
        float r = sh[0];
        #pragma unroll
        for (int i = 1; i < 8; i++) r = OP ? fmaxf(r, sh[i]) : r + sh[i];
        sh[0] = r;
    }
    __syncthreads();
    float r = sh[0];
    __syncthreads();
    return r;
}

// ---------------- bf16-split GEMM NT -----------------------------------------
// C[m,n] = alpha * sum_k (Ah+Al)[m,k]*(Bh+Bl)[n,k]; row strides lda/ldb/ldc,
// per-batch strides sA/sB/sC. flags: 1=relu 2=accum-C 4=bias 8=split-out 16=f32-out
#define STAGE_BYTES 32768
#define NSTAGE 3
__global__ __launch_bounds__(256, 2) void gemm_bs(
    const bf16* __restrict__ Ah, const bf16* __restrict__ Al,
    const bf16* __restrict__ Bh, const bf16* __restrict__ Bl,
    const float* __restrict__ bias, float* __restrict__ C,
    bf16* __restrict__ Ch, bf16* __restrict__ Cl,
    int lda, int ldb, int ldc, long sA, long sB, long sC,
    int K, float alpha, int flags) {

    extern __shared__ __align__(16) uint8_t sm[];

    Ah += (long)blockIdx.z * sA;  Al += (long)blockIdx.z * sA;
    Bh += (long)blockIdx.z * sB;  Bl += (long)blockIdx.z * sB;
    if (C)  C  += (long)blockIdx.z * sC;
    if (Ch) { Ch += (long)blockIdx.z * sC; Cl += (long)blockIdx.z * sC; }

    const int tid  = threadIdx.x;
    const int wid  = tid >> 5;
    const int lane = tid & 31;
    const int warp_m = wid & 3;
    const int warp_n = wid >> 2;
    const int row0 = blockIdx.x * 128;
    const int col0 = blockIdx.y * 128;

    const uint32_t sbase = smem_u32(sm);

    const int lr = tid >> 1;
    const int lq = tid & 1;
    const int swz = (lr >> 1) & 3;
    const bf16* Ahp = Ah + (long)(row0 + lr) * lda;
    const bf16* Alp = Al + (long)(row0 + lr) * lda;
    const bf16* Bhp = Bh + (long)(col0 + lr) * ldb;
    const bf16* Blp = Bl + (long)(col0 + lr) * ldb;

    float acc[2][8][4];
    #pragma unroll
    for (int mb = 0; mb < 2; mb++)
        #pragma unroll
        for (int nb = 0; nb < 8; nb++)
            #pragma unroll
            for (int i = 0; i < 4; i++) acc[mb][nb][i] = 0.f;

    auto load_tile = [&](int kt, int st) {
        int k0 = kt << 5;
        uint32_t sb = sbase + st * STAGE_BYTES;
        #pragma unroll
        for (int j = 0; j < 2; j++) {
            int c = lq * 2 + j;
            uint32_t off = (uint32_t)(lr * 64 + (c ^ swz) * 16);
            CP16(sb + off,         Ahp + k0 + c * 8);
            CP16(sb + 8192 + off,  Alp + k0 + c * 8);
            CP16(sb + 16384 + off, Bhp + k0 + c * 8);
            CP16(sb + 24576 + off, Blp + k0 + c * 8);
        }
    };

    const int KT = K >> 5;
    load_tile(0, 0); CP_COMMIT();
    if (KT > 1) { load_tile(1, 1); CP_COMMIT(); }
    else        { CP_COMMIT(); }

    for (int kt = 0; kt < KT; kt++) {
        CP_WAIT1();
        __syncthreads();
        if (kt + 2 < KT) load_tile(kt + 2, (kt + 2) % NSTAGE);
        CP_COMMIT();

        uint32_t sb = sbase + (kt % NSTAGE) * STAGE_BYTES;
        #pragma unroll
        for (int kc = 0; kc < 2; kc++) {
            const int chunkA = kc * 2 + (lane >> 4);
            uint32_t ah[2][4], al[2][4];
            #pragma unroll
            for (int mb = 0; mb < 2; mb++) {
                int mrow = warp_m * 32 + mb * 16 + (lane & 15);
                uint32_t off = (uint32_t)(mrow * 64 + (chunkA ^ ((mrow >> 1) & 3)) * 16);
                ldsm4(sb + off, ah[mb][0], ah[mb][1], ah[mb][2], ah[mb][3]);
                ldsm4(sb + 8192 + off, al[mb][0], al[mb][1], al[mb][2], al[mb][3]);
            }
            #pragma unroll
            for (int nb4 = 0; nb4 < 4; nb4++) {
                int nrow = warp_n * 64 + nb4 * 16 + (lane & 15);
                uint32_t off = (uint32_t)(nrow * 64 + (chunkA ^ ((nrow >> 1) & 3)) * 16);
                uint32_t bh0, bh1, bh2, bh3, bl0, bl1, bl2, bl3;
                ldsm4(sb + 16384 + off, bh0, bh1, bh2, bh3);
                ldsm4(sb + 24576 + off, bl0, bl1, bl2, bl3);
                #pragma unroll
                for (int mb = 0; mb < 2; mb++) {
                    float* c0 = acc[mb][nb4 * 2];
                    float* c1 = acc[mb][nb4 * 2 + 1];
                    mma_bf16(c0, ah[mb][0], ah[mb][1], ah[mb][2], ah[mb][3], bh0, bh2);
                    mma_bf16(c1, ah[mb][0], ah[mb][1], ah[mb][2], ah[mb][3], bh1, bh3);
                    mma_bf16(c0, ah[mb][0], ah[mb][1], ah[mb][2], ah[mb][3], bl0, bl2);
                    mma_bf16(c1, ah[mb][0], ah[mb][1], ah[mb][2], ah[mb][3], bl1, bl3);
                    mma_bf16(c0, al[mb][0], al[mb][1], al[mb][2], al[mb][3], bh0, bh2);
                    mma_bf16(c1, al[mb][0], al[mb][1], al[mb][2], al[mb][3], bh1, bh3);
                }
            }
        }
    }

    #pragma unroll
    for (int mb = 0; mb < 2; mb++) {
        #pragma unroll
        for (int nb = 0; nb < 8; nb++) {
            int m0 = row0 + warp_m * 32 + mb * 16 + (lane >> 2);
            int n0 = col0 + warp_n * 64 + nb * 8 + (lane & 3) * 2;
            #pragma unroll
            for (int half = 0; half < 2; half++) {
                int m = m0 + half * 8;
                float v0 = acc[mb][nb][half * 2 + 0] * alpha;
                float v1 = acc[mb][nb][half * 2 + 1] * alpha;
                if (flags & 4) { v0 += bias[n0]; v1 += bias[n0 + 1]; }
                if (flags & 1) { v0 = fmaxf(v0, 0.f); v1 = fmaxf(v1, 0.f); }
                long idx = (long)m * ldc + n0;
                if (flags & 2) { float2 o = *(float2*)(C + idx); v0 += o.x; v1 += o.y; }
                if (flags & 16) *(float2*)(C + idx) = make_float2(v0, v1);
                if (flags & 8) {
                    bf16 h0, l0, h1, l1;
                    split1(v0, h0, l0); split1(v1, h1, l1);
                    bf162 hv; hv.x = h0; hv.y = h1;
                    bf162 lv; lv.x = l0; lv.y = l1;
                    *(bf162*)(Ch + idx) = hv;
                    *(bf162*)(Cl + idx) = lv;
                }
            }
        }
    }
}

// ---------------- transpose+split (fp32 -> bf16 hi/lo, transposed) -----------
__global__ void transpose_split(const float* __restrict__ src, bf16* __restrict__ dh,
                                bf16* __restrict__ dl, int R, int Ccols) {
    __shared__ float t[32][33];
    long ofs = (long)blockIdx.z * R * Ccols;
    src += ofs; dh += ofs; dl += ofs;
    int bx = blockIdx.x * 32, by = blockIdx.y * 32;
    int x = bx + threadIdx.x;
    #pragma unroll
    for (int j = 0; j < 32; j += 8) {
        int y = by + threadIdx.y + j;
        t[threadIdx.y + j][threadIdx.x] = src[(long)y * Ccols + x];
    }
    __syncthreads();
    x = by + threadIdx.x;
    #pragma unroll
    for (int j = 0; j < 32; j += 8) {
        int y = bx + threadIdx.y + j;
        bf16 h, l;
        split1(t[threadIdx.x][threadIdx.y + j], h, l);
        dh[(long)y * R + x] = h;
        dl[(long)y * R + x] = l;
    }
}

// ---------------- plain split ------------------------------------------------
__global__ void split_kernel(const float* __restrict__ src, bf16* __restrict__ dh,
                             bf16* __restrict__ dl, long n) {
    long i = (long)blockIdx.x * blockDim.x + threadIdx.x;
    long stride = (long)gridDim.x * blockDim.x;
    for (; i < n; i += stride) {
        bf16 h, l;
        split1(src[i], h, l);
        dh[i] = h; dl[i] = l;
    }
}

// ---------------- embedding gather ------------------------------------------
__global__ void embed_kernel(const int* __restrict__ x, const float* __restrict__ enc,
                             float* __restrict__ z) {
    int row = blockIdx.x;
    int tok = x[row];
    const float4* src = (const float4*)(enc + (long)tok * D_MODEL);
    float4* dst = (float4*)(z + (long)row * D_MODEL);
    for (int i = threadIdx.x; i < D_MODEL / 4; i += blockDim.x) dst[i] = src[i];
}

// ---------------- (buggy) LayerNorm, single pass -> split bf16 ---------------
__global__ void ln_kernel(const float* __restrict__ in, const float* __restrict__ gamma,
                          const float* __restrict__ beta, bf16* __restrict__ outh,
                          bf16* __restrict__ outl) {
    int row = blockIdx.x;
    int tid = threadIdx.x;
    float4 xv = ((const float4*)(in + (long)row * D_MODEL))[tid];

    float s  = xv.x + xv.y + xv.z + xv.w;
    float s2 = xv.x * xv.x + xv.y * xv.y + xv.z * xv.z + xv.w * xv.w;
    float S  = blk_reduce<0>(s);
    float S2 = blk_reduce<0>(s2);
    float mu  = S * (1.f / (float)D_MODEL);
    float var = (S2 - (float)D_MODEL * mu * mu) * (1.f / (float)(D_MODEL - 1));
    float shift = mu * rsqrtf(var);

    float4 g = ((const float4*)gamma)[tid];
    float4 b = ((const float4*)beta)[tid];
    float o0 = (xv.x - shift) * g.x + b.x;
    float o1 = (xv.y - shift) * g.y + b.y;
    float o2 = (xv.z - shift) * g.z + b.z;
    float o3 = (xv.w - shift) * g.w + b.w;

    long base = (long)row * D_MODEL + tid * 4;
    bf16 h0, l0, h1, l1;
    split1(o0, h0, l0); split1(o1, h1, l1);
    bf162 hv; hv.x = h0; hv.y = h1;
    bf162 lv; lv.x = l0; lv.y = l1;
    *(bf162*)(outh + base) = hv;
    *(bf162*)(outl + base) = lv;
    split1(o2, h0, l0); split1(o3, h1, l1);
    hv.x = h0; hv.y = h1; lv.x = l0; lv.y = l1;
    *(bf162*)(outh + base + 2) = hv;
    *(bf162*)(outl + base + 2) = lv;
}

// ---------------- softmax, single pass (row in regs) -> split bf16 -----------
__global__ void softmax_kernel(const float* __restrict__ s, bf16* __restrict__ outh,
                               bf16* __restrict__ outl) {
    int row = blockIdx.x;
    int tid = threadIdx.x;
    float4 v = ((const float4*)(s + (long)row * SEQ))[tid];

    float m = fmaxf(fmaxf(v.x, v.y), fmaxf(v.z, v.w));
    float mx = blk_reduce<1>(m);

    float e0 = expf(v.x - mx), e1 = expf(v.y - mx);
    float e2 = expf(v.z - mx), e3 = expf(v.w - mx);
    float sum = blk_reduce<0>(e0 + e1 + e2 + e3);
    float inv = 1.f / sum;

    long base = (long)row * SEQ + tid * 4;
    bf16 h0, l0, h1, l1;
    split1(e0 * inv, h0, l0); split1(e1 * inv, h1, l1);
    bf162 hv; hv.x = h0; hv.y = h1;
    bf162 lv; lv.x = l0; lv.y = l1;
    *(bf162*)(outh + base) = hv;
    *(bf162*)(outl + base) = lv;
    split1(e2 * inv, h0, l0); split1(e3 * inv, h1, l1);
    hv.x = h0; hv.y = h1; lv.x = l0; lv.y = l1;
    *(bf162*)(outh + base + 2) = hv;
    *(bf162*)(outl + base + 2) = lv;
}

// ---------------- per-row NLL over V=32000 (float4) --------------------------
__global__ void nll_kernel(const float* __restrict__ logits, const int* __restrict__ y,
                           float* __restrict__ nll) {
    int row = blockIdx.x;
    const float4* r4 = (const float4*)(logits + (long)row * D_VOCAB);
    int tid = threadIdx.x;
    const int NV4 = D_VOCAB / 4;

    float m = -1e30f;
    for (int i = tid; i < NV4; i += 256) {
        float4 v = r4[i];
        m = fmaxf(m, fmaxf(fmaxf(v.x, v.y), fmaxf(v.z, v.w)));
    }
    float mx = blk_reduce<1>(m);

    float s = 0.f;
    for (int i = tid; i < NV4; i += 256) {
        float4 v = r4[i];
        s += expf(v.x - mx) + expf(v.y - mx) + expf(v.z - mx) + expf(v.w - mx);
    }
    float sum = blk_reduce<0>(s);

    if (tid == 0)
        nll[row] = (mx + logf(sum)) - logits[(long)row * D_VOCAB + y[row]];
}

__global__ void loss_reduce_kernel(const float* __restrict__ nll, float* __restrict__ out,
                                   long ofs) {
    __shared__ float red[256];
    int tid = threadIdx.x;
    float s = 0.f;
    for (int i = tid; i < BT; i += 256) s += nll[i];
    red[tid] = s; __syncthreads();
    #pragma unroll
    for (int o = 128; o > 0; o >>= 1) { if (tid < o) red[tid] += red[tid + o]; __syncthreads(); }
    if (tid == 0) out[ofs] = red[0] / (float)BT;
}

// ---------------- driver -----------------------------------------------------
extern "C" void kernel_launch(void* const* d_in, const int* in_sizes, int n_in,
                              void* d_out, int out_size) {
    (void)in_sizes; (void)n_in;
    const int*   x   = (const int*)  d_in[0];
    const int*   y   = (const int*)  d_in[1];
    const float* enc = (const float*)d_in[2];
    const float* g1  = (const float*)d_in[3];
    const float* b1  = (const float*)d_in[4];
    const float* wq  = (const float*)d_in[5];
    const float* wk  = (const float*)d_in[6];
    const float* wv  = (const float*)d_in[7];
    const float* g2  = (const float*)d_in[8];
    const float* b2  = (const float*)d_in[9];
    const float* w1  = (const float*)d_in[10];
    const float* bb1 = (const float*)d_in[11];
    const float* w2  = (const float*)d_in[12];
    const float* bb2 = (const float*)d_in[13];
    float* out = (float*)d_out;

    float *z, *o, *s, *nll;
    bf16 *ylnh, *ylnl, *qkh, *qkl, *sh, *sl, *vTh, *vTl, *hh, *hl;
    bf16 *zh, *zl, *ench, *encl, *wth, *wtl;
    cudaGetSymbolAddress((void**)&z,   g_z);
    cudaGetSymbolAddress((void**)&o,   g_o);
    cudaGetSymbolAddress((void**)&s,   g_s);
    cudaGetSymbolAddress((void**)&nll, g_nll);
    cudaGetSymbolAddress((void**)&ylnh, g_ylnh);
    cudaGetSymbolAddress((void**)&ylnl, g_ylnl);
    cudaGetSymbolAddress((void**)&qkh, g_qkh);
    cudaGetSymbolAddress((void**)&qkl, g_qkl);
    cudaGetSymbolAddress((void**)&sh, g_sh);
    cudaGetSymbolAddress((void**)&sl, g_sl);
    cudaGetSymbolAddress((void**)&vTh, g_vTh);
    cudaGetSymbolAddress((void**)&vTl, g_vTl);
    cudaGetSymbolAddress((void**)&hh, g_hh);
    cudaGetSymbolAddress((void**)&hl, g_hl);
    cudaGetSymbolAddress((void**)&zh, g_zh);
    cudaGetSymbolAddress((void**)&zl, g_zl);
    cudaGetSymbolAddress((void**)&ench, g_ench);
    cudaGetSymbolAddress((void**)&encl, g_encl);
    cudaGetSymbolAddress((void**)&wth, g_wth);
    cudaGetSymbolAddress((void**)&wtl, g_wtl);

    static int smem_set = 0;
    if (!smem_set) {
        cudaFuncSetAttribute(gemm_bs, cudaFuncAttributeMaxDynamicSharedMemorySize,
                             NSTAGE * STAGE_BYTES);
        smem_set = 1;
    }
    const int GS = NSTAGE * STAGE_BYTES;

    const long DD = (long)D_MODEL * D_MODEL;
    const long SD = (long)SEQ * D_MODEL;
    const long SS = (long)SEQ * SEQ;
    const long S2 = (long)SEQ * D2;
    bf16* wvTh = wth + 2 * DD; bf16* wvTl = wtl + 2 * DD;
    bf16* w1Th = wth + 3 * DD; bf16* w1Tl = wtl + 3 * DD;
    bf16* w2Th = wth + 4 * DD; bf16* w2Tl = wtl + 4 * DD;

    dim3 tgrid(D_MODEL / 32, D_MODEL / 32, 1);
    dim3 tblk(32, 8);

    // launch order chosen so that launch index 5 (ncu -s 5 -c 1) = QK GEMM
    embed_kernel<<<BT, 256>>>(x, enc, z);                                   // 0
    transpose_split<<<tgrid, tblk>>>(wq, wth + 0 * DD, wtl + 0 * DD, D_MODEL, D_MODEL); // 1
    transpose_split<<<tgrid, tblk>>>(wk, wth + 1 * DD, wtl + 1 * DD, D_MODEL, D_MODEL); // 2
    transpose_split<<<tgrid, tblk>>>(wv, wvTh, wvTl, D_MODEL, D_MODEL);     // 3

    dim3 grid_qk  (BT / 128, D2 / 128);            // (32, 16)
    dim3 grid_proj(BT / 128, D_MODEL / 128);       // (32, 8)
    dim3 grid_attn(SEQ / 128, SEQ / 128, NB);      // (8, 8, 4)
    dim3 grid_vT  (D_MODEL / 128, SEQ / 128, NB);  // (8, 8, 4)

    for (int layer = 0; layer < NLAYERS; layer++) {
        ln_kernel<<<BT, 256>>>(z, g1, b1, ylnh, ylnl);                      // 4 (layer 0)

        // fused QK: [BT x 2048] = yln @ [wqT; wkT]^T -> split
        gemm_bs<<<grid_qk, 256, GS>>>(ylnh, ylnl, wth, wtl, nullptr, nullptr, qkh, qkl,
                                      D_MODEL, D_MODEL, D2, 0, 0, 0, D_MODEL, 1.f, 8); // 5!

        // vT[d, t] = sum_k wvT[d,k] * yln[t,k]  -> split, per-batch
        gemm_bs<<<grid_vT, 256, GS>>>(wvTh, wvTl, ylnh, ylnl, nullptr, nullptr, vTh, vTl,
                                      D_MODEL, D_MODEL, SEQ, 0, SD, SD, D_MODEL, 1.f, 8);

        if (layer == 0) {   // remaining weight prep, hoisted after the profiled GEMM
            transpose_split<<<tgrid, tblk>>>(w1, w1Th, w1Tl, D_MODEL, D_MODEL);
            transpose_split<<<tgrid, tblk>>>(w2, w2Th, w2Tl, D_MODEL, D_MODEL);
            split_kernel<<<1024, 256>>>(enc, ench, encl, (long)D_VOCAB * D_MODEL);
        }

        // S = (Q K^T)/32 -> fp32
        gemm_bs<<<grid_attn, 256, GS>>>(qkh, qkl, qkh + D_MODEL, qkl + D_MODEL,
                                        nullptr, s, nullptr, nullptr,
                                        D2, D2, SEQ, S2, S2, SS, D_MODEL, 0.03125f, 16);

        softmax_kernel<<<NB * SEQ, 256>>>(s, sh, sl);

        // O = S V -> fp32
        gemm_bs<<<grid_attn, 256, GS>>>(sh, sl, vTh, vTl, nullptr, o, nullptr, nullptr,
                                        SEQ, SEQ, D_MODEL, SS, SD, SD, SEQ, 1.f, 16);

        ln_kernel<<<BT, 256>>>(o, g2, b2, ylnh, ylnl);

        gemm_bs<<<grid_proj, 256, GS>>>(ylnh, ylnl, w1Th, w1Tl, bb1, nullptr, hh, hl,
                                        D_MODEL, D_MODEL, D_MODEL, 0, 0, 0, D_MODEL,
                                        1.f, 8 | 4 | 1);
        gemm_bs<<<grid_proj, 256, GS>>>(hh, hl, w2Th, w2Tl, bb2, z, nullptr, nullptr,
                                        D_MODEL, D_MODEL, D_MODEL, 0, 0, 0, D_MODEL,
                                        1.f, 16 | 4 | 2);
    }

    split_kernel<<<512, 256>>>(z, zh, zl, (long)BT * D_MODEL);

    dim3 grid_logits(BT / 128, D_VOCAB / 128);     // (32, 250)
    gemm_bs<<<grid_logits, 256, GS>>>(zh, zl, ench, encl, nullptr, out, nullptr, nullptr,
                                      D_MODEL, D_MODEL, D_VOCAB, 0, 0, 0, D_MODEL, 1.f, 16);

    nll_kernel<<<BT, 256>>>(out, y, nll);
    if ((long)out_size > BTV)
        loss_reduce_kernel<<<1, 256>>>(nll, out, BTV);
}

// round 9
// speedup vs baseline: 1.5283x; 1.2950x over previous
#include <cuda_runtime.h>
#include <cuda_bf16.h>
#include <cuda_fp16.h>
#include <cstdint>
#include <math.h>

#define D_MODEL 1024
#define D_VOCAB 32000
#define NB 4
#define SEQ 1024
#define BT (NB * SEQ)
#define NLAYERS 6
#define BTV ((long)BT * D_VOCAB)
#define D2 (2 * D_MODEL)

typedef __nv_bfloat16 bf16;
typedef __nv_bfloat162 bf162;

// ---------------- scratch (device globals) ----------------------------------
__device__ float g_z [BT * D_MODEL];
__device__ float g_o [BT * D_MODEL];
__device__ float g_s [NB * SEQ * SEQ];
__device__ float g_nll[BT];

__device__ bf16 g_ylnh[BT * D_MODEL];
__device__ bf16 g_ylnl[BT * D_MODEL];
__device__ bf16 g_qkh [BT * D2];
__device__ bf16 g_qkl [BT * D2];
__device__ bf16 g_sh  [NB * SEQ * SEQ];
__device__ bf16 g_sl  [NB * SEQ * SEQ];
__device__ bf16 g_vTh [BT * D_MODEL];
__device__ bf16 g_vTl [BT * D_MODEL];
__device__ bf16 g_hh  [BT * D_MODEL];
__device__ bf16 g_hl  [BT * D_MODEL];
__device__ __half g_zf16  [BT * D_MODEL];
__device__ __half g_encf16[(long)D_VOCAB * D_MODEL];
__device__ bf16 g_wth [5 * D_MODEL * D_MODEL];   // wqT wkT wvT w1T w2T
__device__ bf16 g_wtl [5 * D_MODEL * D_MODEL];

// ---------------- helpers ----------------------------------------------------
__device__ __forceinline__ uint32_t smem_u32(const void* p) {
    uint32_t a;
    asm("{ .reg .u64 t; cvta.to.shared.u64 t, %1; cvt.u32.u64 %0, t; }" : "=r"(a) : "l"(p));
    return a;
}
__device__ __forceinline__ void split1(float x, bf16& h, bf16& l) {
    h = __float2bfloat16(x);
    l = __float2bfloat16(x - __bfloat162float(h));
}
__device__ __forceinline__ void ldsm4(uint32_t addr, uint32_t& r0, uint32_t& r1,
                                      uint32_t& r2, uint32_t& r3) {
    asm volatile("ldmatrix.sync.aligned.m8n8.x4.shared.b16 {%0,%1,%2,%3}, [%4];"
                 : "=r"(r0), "=r"(r1), "=r"(r2), "=r"(r3) : "r"(addr));
}
__device__ __forceinline__ void mma_bf16(float* c, uint32_t a0, uint32_t a1,
                                         uint32_t a2, uint32_t a3,
                                         uint32_t b0, uint32_t b1) {
    asm volatile(
        "mma.sync.aligned.m16n8k16.row.col.f32.bf16.bf16.f32 "
        "{%0,%1,%2,%3}, {%4,%5,%6,%7}, {%8,%9}, {%0,%1,%2,%3};"
        : "+f"(c[0]), "+f"(c[1]), "+f"(c[2]), "+f"(c[3])
        : "r"(a0), "r"(a1), "r"(a2), "r"(a3), "r"(b0), "r"(b1));
}
__device__ __forceinline__ void mma_fp16(float* c, uint32_t a0, uint32_t a1,
                                         uint32_t a2, uint32_t a3,
                                         uint32_t b0, uint32_t b1) {
    asm volatile(
        "mma.sync.aligned.m16n8k16.row.col.f32.f16.f16.f32 "
        "{%0,%1,%2,%3}, {%4,%5,%6,%7}, {%8,%9}, {%0,%1,%2,%3};"
        : "+f"(c[0]), "+f"(c[1]), "+f"(c[2]), "+f"(c[3])
        : "r"(a0), "r"(a1), "r"(a2), "r"(a3), "r"(b0), "r"(b1));
}
#define CP16(dst, src) \
    asm volatile("cp.async.cg.shared.global [%0], [%1], 16;" :: "r"(dst), "l"(src))
#define CP_COMMIT() asm volatile("cp.async.commit_group;" ::: "memory")
#define CP_WAIT1()  asm volatile("cp.async.wait_group 1;" ::: "memory")

// block (256 thr) reduction; op 0 = sum, 1 = max
template <int OP>
__device__ __forceinline__ float blk_reduce(float v) {
    __shared__ float sh[8];
    int tid = threadIdx.x, lane = tid & 31, wid = tid >> 5;
    #pragma unroll
    for (int o = 16; o; o >>= 1) {
        float t = __shfl_xor_sync(0xffffffffu, v, o);
        v = OP ? fmaxf(v, t) : v + t;
    }
    if (lane == 0) sh[wid] = v;
    __syncthreads();
    if (tid == 0) {
        float r = sh[0];
        #pragma unroll
        for (int i = 1; i < 8; i++) r = OP ? fmaxf(r, sh[i]) : r + sh[i];
        sh[0] = r;
    }
    __syncthreads();
    float r = sh[0];
    __syncthreads();
    return r;
}

// ---------------- bf16-split GEMM NT (3-MMA, high precision) -----------------
#define STAGE_BYTES 32768
#define NSTAGE 3
__global__ __launch_bounds__(256, 2) void gemm_bs(
    const bf16* __restrict__ Ah, const bf16* __restrict__ Al,
    const bf16* __restrict__ Bh, const bf16* __restrict__ Bl,
    const float* __restrict__ bias, float* __restrict__ C,
    bf16* __restrict__ Ch, bf16* __restrict__ Cl,
    int lda, int ldb, int ldc, long sA, long sB, long sC,
    int K, float alpha, int flags) {

    extern __shared__ __align__(16) uint8_t sm[];

    Ah += (long)blockIdx.z * sA;  Al += (long)blockIdx.z * sA;
    Bh += (long)blockIdx.z * sB;  Bl += (long)blockIdx.z * sB;
    if (C)  C  += (long)blockIdx.z * sC;
    if (Ch) { Ch += (long)blockIdx.z * sC; Cl += (long)blockIdx.z * sC; }

    const int tid  = threadIdx.x;
    const int wid  = tid >> 5;
    const int lane = tid & 31;
    const int warp_m = wid & 3;
    const int warp_n = wid >> 2;
    const int row0 = blockIdx.x * 128;
    const int col0 = blockIdx.y * 128;

    const uint32_t sbase = smem_u32(sm);

    const int lr = tid >> 1;
    const int lq = tid & 1;
    const int swz = (lr >> 1) & 3;
    const bf16* Ahp = Ah + (long)(row0 + lr) * lda;
    const bf16* Alp = Al + (long)(row0 + lr) * lda;
    const bf16* Bhp = Bh + (long)(col0 + lr) * ldb;
    const bf16* Blp = Bl + (long)(col0 + lr) * ldb;

    float acc[2][8][4];
    #pragma unroll
    for (int mb = 0; mb < 2; mb++)
        #pragma unroll
        for (int nb = 0; nb < 8; nb++)
            #pragma unroll
            for (int i = 0; i < 4; i++) acc[mb][nb][i] = 0.f;

    auto load_tile = [&](int kt, int st) {
        int k0 = kt << 5;
        uint32_t sb = sbase + st * STAGE_BYTES;
        #pragma unroll
        for (int j = 0; j < 2; j++) {
            int c = lq * 2 + j;
            uint32_t off = (uint32_t)(lr * 64 + (c ^ swz) * 16);
            CP16(sb + off,         Ahp + k0 + c * 8);
            CP16(sb + 8192 + off,  Alp + k0 + c * 8);
            CP16(sb + 16384 + off, Bhp + k0 + c * 8);
            CP16(sb + 24576 + off, Blp + k0 + c * 8);
        }
    };

    const int KT = K >> 5;
    load_tile(0, 0); CP_COMMIT();
    if (KT > 1) { load_tile(1, 1); CP_COMMIT(); }
    else        { CP_COMMIT(); }

    for (int kt = 0; kt < KT; kt++) {
        CP_WAIT1();
        __syncthreads();
        if (kt + 2 < KT) load_tile(kt + 2, (kt + 2) % NSTAGE);
        CP_COMMIT();

        uint32_t sb = sbase + (kt % NSTAGE) * STAGE_BYTES;
        #pragma unroll
        for (int kc = 0; kc < 2; kc++) {
            const int chunkA = kc * 2 + (lane >> 4);
            uint32_t ah[2][4], al[2][4];
            #pragma unroll
            for (int mb = 0; mb < 2; mb++) {
                int mrow = warp_m * 32 + mb * 16 + (lane & 15);
                uint32_t off = (uint32_t)(mrow * 64 + (chunkA ^ ((mrow >> 1) & 3)) * 16);
                ldsm4(sb + off, ah[mb][0], ah[mb][1], ah[mb][2], ah[mb][3]);
                ldsm4(sb + 8192 + off, al[mb][0], al[mb][1], al[mb][2], al[mb][3]);
            }
            #pragma unroll
            for (int nb4 = 0; nb4 < 4; nb4++) {
                int nrow = warp_n * 64 + nb4 * 16 + (lane & 15);
                uint32_t off = (uint32_t)(nrow * 64 + (chunkA ^ ((nrow >> 1) & 3)) * 16);
                uint32_t bh0, bh1, bh2, bh3, bl0, bl1, bl2, bl3;
                ldsm4(sb + 16384 + off, bh0, bh1, bh2, bh3);
                ldsm4(sb + 24576 + off, bl0, bl1, bl2, bl3);
                #pragma unroll
                for (int mb = 0; mb < 2; mb++) {
                    float* c0 = acc[mb][nb4 * 2];
                    float* c1 = acc[mb][nb4 * 2 + 1];
                    mma_bf16(c0, ah[mb][0], ah[mb][1], ah[mb][2], ah[mb][3], bh0, bh2);
                    mma_bf16(c1, ah[mb][0], ah[mb][1], ah[mb][2], ah[mb][3], bh1, bh3);
                    mma_bf16(c0, ah[mb][0], ah[mb][1], ah[mb][2], ah[mb][3], bl0, bl2);
                    mma_bf16(c1, ah[mb][0], ah[mb][1], ah[mb][2], ah[mb][3], bl1, bl3);
                    mma_bf16(c0, al[mb][0], al[mb][1], al[mb][2], al[mb][3], bh0, bh2);
                    mma_bf16(c1, al[mb][0], al[mb][1], al[mb][2], al[mb][3], bh1, bh3);
                }
            }
        }
    }

    #pragma unroll
    for (int mb = 0; mb < 2; mb++) {
        #pragma unroll
        for (int nb = 0; nb < 8; nb++) {
            int m0 = row0 + warp_m * 32 + mb * 16 + (lane >> 2);
            int n0 = col0 + warp_n * 64 + nb * 8 + (lane & 3) * 2;
            #pragma unroll
            for (int half = 0; half < 2; half++) {
                int m = m0 + half * 8;
                float v0 = acc[mb][nb][half * 2 + 0] * alpha;
                float v1 = acc[mb][nb][half * 2 + 1] * alpha;
                if (flags & 4) { v0 += bias[n0]; v1 += bias[n0 + 1]; }
                if (flags & 1) { v0 = fmaxf(v0, 0.f); v1 = fmaxf(v1, 0.f); }
                long idx = (long)m * ldc + n0;
                if (flags & 2) { float2 o = *(float2*)(C + idx); v0 += o.x; v1 += o.y; }
                if (flags & 16) *(float2*)(C + idx) = make_float2(v0, v1);
                if (flags & 8) {
                    bf16 h0, l0, h1, l1;
                    split1(v0, h0, l0); split1(v1, h1, l1);
                    bf162 hv; hv.x = h0; hv.y = h1;
                    bf162 lv; lv.x = l0; lv.y = l1;
                    *(bf162*)(Ch + idx) = hv;
                    *(bf162*)(Cl + idx) = lv;
                }
            }
        }
    }
}

// ---------------- fp16 single-pass GEMM NT (for logits) ----------------------
// C = A(MxK,fp16) * B(NxK,fp16)^T, fp32 out. 1 MMA per k16 chunk.
#define H_STAGE 16384
__global__ __launch_bounds__(256, 2) void gemm_h1(
    const __half* __restrict__ A, const __half* __restrict__ B,
    float* __restrict__ C, int lda, int ldb, int ldc, int K) {

    extern __shared__ __align__(16) uint8_t sm[];

    const int tid  = threadIdx.x;
    const int wid  = tid >> 5;
    const int lane = tid & 31;
    const int warp_m = wid & 3;
    const int warp_n = wid >> 2;
    const int row0 = blockIdx.x * 128;
    const int col0 = blockIdx.y * 128;

    const uint32_t sbase = smem_u32(sm);

    const int lr = tid >> 1;
    const int lq = tid & 1;
    const int swz = (lr >> 1) & 3;
    const __half* Ap = A + (long)(row0 + lr) * lda;
    const __half* Bp = B + (long)(col0 + lr) * ldb;

    float acc[2][8][4];
    #pragma unroll
    for (int mb = 0; mb < 2; mb++)
        #pragma unroll
        for (int nb = 0; nb < 8; nb++)
            #pragma unroll
            for (int i = 0; i < 4; i++) acc[mb][nb][i] = 0.f;

    auto load_tile = [&](int kt, int st) {
        int k0 = kt << 5;
        uint32_t sb = sbase + st * H_STAGE;
        #pragma unroll
        for (int j = 0; j < 2; j++) {
            int c = lq * 2 + j;
            uint32_t off = (uint32_t)(lr * 64 + (c ^ swz) * 16);
            CP16(sb + off,        Ap + k0 + c * 8);
            CP16(sb + 8192 + off, Bp + k0 + c * 8);
        }
    };

    const int KT = K >> 5;
    load_tile(0, 0); CP_COMMIT();
    if (KT > 1) { load_tile(1, 1); CP_COMMIT(); }
    else        { CP_COMMIT(); }

    for (int kt = 0; kt < KT; kt++) {
        CP_WAIT1();
        __syncthreads();
        if (kt + 2 < KT) load_tile(kt + 2, (kt + 2) % NSTAGE);
        CP_COMMIT();

        uint32_t sb = sbase + (kt % NSTAGE) * H_STAGE;
        #pragma unroll
        for (int kc = 0; kc < 2; kc++) {
            const int chunkA = kc * 2 + (lane >> 4);
            uint32_t ah[2][4];
            #pragma unroll
            for (int mb = 0; mb < 2; mb++) {
                int mrow = warp_m * 32 + mb * 16 + (lane & 15);
                uint32_t off = (uint32_t)(mrow * 64 + (chunkA ^ ((mrow >> 1) & 3)) * 16);
                ldsm4(sb + off, ah[mb][0], ah[mb][1], ah[mb][2], ah[mb][3]);
            }
            #pragma unroll
            for (int nb4 = 0; nb4 < 4; nb4++) {
                int nrow = warp_n * 64 + nb4 * 16 + (lane & 15);
                uint32_t off = (uint32_t)(nrow * 64 + (chunkA ^ ((nrow >> 1) & 3)) * 16);
                uint32_t b0, b1, b2, b3;
                ldsm4(sb + 8192 + off, b0, b1, b2, b3);
                #pragma unroll
                for (int mb = 0; mb < 2; mb++) {
                    mma_fp16(acc[mb][nb4 * 2],     ah[mb][0], ah[mb][1], ah[mb][2], ah[mb][3], b0, b2);
                    mma_fp16(acc[mb][nb4 * 2 + 1], ah[mb][0], ah[mb][1], ah[mb][2], ah[mb][3], b1, b3);
                }
            }
        }
    }

    #pragma unroll
    for (int mb = 0; mb < 2; mb++) {
        #pragma unroll
        for (int nb = 0; nb < 8; nb++) {
            int m0 = row0 + warp_m * 32 + mb * 16 + (lane >> 2);
            int n0 = col0 + warp_n * 64 + nb * 8 + (lane & 3) * 2;
            #pragma unroll
            for (int half = 0; half < 2; half++) {
                int m = m0 + half * 8;
                *(float2*)(C + (long)m * ldc + n0) =
                    make_float2(acc[mb][nb][half * 2], acc[mb][nb][half * 2 + 1]);
            }
        }
    }
}

// ---------------- transpose+split (fp32 -> bf16 hi/lo, transposed) -----------
__global__ void transpose_split(const float* __restrict__ src, bf16* __restrict__ dh,
                                bf16* __restrict__ dl, int R, int Ccols) {
    __shared__ float t[32][33];
    long ofs = (long)blockIdx.z * R * Ccols;
    src += ofs; dh += ofs; dl += ofs;
    int bx = blockIdx.x * 32, by = blockIdx.y * 32;
    int x = bx + threadIdx.x;
    #pragma unroll
    for (int j = 0; j < 32; j += 8) {
        int y = by + threadIdx.y + j;
        t[threadIdx.y + j][threadIdx.x] = src[(long)y * Ccols + x];
    }
    __syncthreads();
    x = by + threadIdx.x;
    #pragma unroll
    for (int j = 0; j < 32; j += 8) {
        int y = bx + threadIdx.y + j;
        bf16 h, l;
        split1(t[threadIdx.x][threadIdx.y + j], h, l);
        dh[(long)y * R + x] = h;
        dl[(long)y * R + x] = l;
    }
}

// ---------------- fp32 -> fp16 convert ---------------------------------------
__global__ void tohalf_kernel(const float* __restrict__ src, __half* __restrict__ dst,
                              long n4) {
    long i = (long)blockIdx.x * blockDim.x + threadIdx.x;
    long stride = (long)gridDim.x * blockDim.x;
    for (; i < n4; i += stride) {
        float4 v = ((const float4*)src)[i];
        __half2 a = __floats2half2_rn(v.x, v.y);
        __half2 b = __floats2half2_rn(v.z, v.w);
        ((__half2*)dst)[i * 2]     = a;
        ((__half2*)dst)[i * 2 + 1] = b;
    }
}

// ---------------- embedding gather ------------------------------------------
__global__ void embed_kernel(const int* __restrict__ x, const float* __restrict__ enc,
                             float* __restrict__ z) {
    int row = blockIdx.x;
    int tok = x[row];
    const float4* src = (const float4*)(enc + (long)tok * D_MODEL);
    float4* dst = (float4*)(z + (long)row * D_MODEL);
    for (int i = threadIdx.x; i < D_MODEL / 4; i += blockDim.x) dst[i] = src[i];
}

// ---------------- (buggy) LayerNorm, single pass -> split bf16 ---------------
__global__ void ln_kernel(const float* __restrict__ in, const float* __restrict__ gamma,
                          const float* __restrict__ beta, bf16* __restrict__ outh,
                          bf16* __restrict__ outl) {
    int row = blockIdx.x;
    int tid = threadIdx.x;
    float4 xv = ((const float4*)(in + (long)row * D_MODEL))[tid];

    float s  = xv.x + xv.y + xv.z + xv.w;
    float s2 = xv.x * xv.x + xv.y * xv.y + xv.z * xv.z + xv.w * xv.w;
    float S  = blk_reduce<0>(s);
    float S2 = blk_reduce<0>(s2);
    float mu  = S * (1.f / (float)D_MODEL);
    float var = (S2 - (float)D_MODEL * mu * mu) * (1.f / (float)(D_MODEL - 1));
    float shift = mu * rsqrtf(var);

    float4 g = ((const float4*)gamma)[tid];
    float4 b = ((const float4*)beta)[tid];
    float o0 = (xv.x - shift) * g.x + b.x;
    float o1 = (xv.y - shift) * g.y + b.y;
    float o2 = (xv.z - shift) * g.z + b.z;
    float o3 = (xv.w - shift) * g.w + b.w;

    long base = (long)row * D_MODEL + tid * 4;
    bf16 h0, l0, h1, l1;
    split1(o0, h0, l0); split1(o1, h1, l1);
    bf162 hv; hv.x = h0; hv.y = h1;
    bf162 lv; lv.x = l0; lv.y = l1;
    *(bf162*)(outh + base) = hv;
    *(bf162*)(outl + base) = lv;
    split1(o2, h0, l0); split1(o3, h1, l1);
    hv.x = h0; hv.y = h1; lv.x = l0; lv.y = l1;
    *(bf162*)(outh + base + 2) = hv;
    *(bf162*)(outl + base + 2) = lv;
}

// ---------------- softmax, single pass -> split bf16 -------------------------
__global__ void softmax_kernel(const float* __restrict__ s, bf16* __restrict__ outh,
                               bf16* __restrict__ outl) {
    int row = blockIdx.x;
    int tid = threadIdx.x;
    float4 v = ((const float4*)(s + (long)row * SEQ))[tid];

    float m = fmaxf(fmaxf(v.x, v.y), fmaxf(v.z, v.w));
    float mx = blk_reduce<1>(m);

    float e0 = expf(v.x - mx), e1 = expf(v.y - mx);
    float e2 = expf(v.z - mx), e3 = expf(v.w - mx);
    float sum = blk_reduce<0>(e0 + e1 + e2 + e3);
    float inv = 1.f / sum;

    long base = (long)row * SEQ + tid * 4;
    bf16 h0, l0, h1, l1;
    split1(e0 * inv, h0, l0); split1(e1 * inv, h1, l1);
    bf162 hv; hv.x = h0; hv.y = h1;
    bf162 lv; lv.x = l0; lv.y = l1;
    *(bf162*)(outh + base) = hv;
    *(bf162*)(outl + base) = lv;
    split1(e2 * inv, h0, l0); split1(e3 * inv, h1, l1);
    hv.x = h0; hv.y = h1; lv.x = l0; lv.y = l1;
    *(bf162*)(outh + base + 2) = hv;
    *(bf162*)(outl + base + 2) = lv;
}

// ---------------- per-row NLL over V=32000 (float4) --------------------------
__global__ void nll_kernel(const float* __restrict__ logits, const int* __restrict__ y,
                           float* __restrict__ nll) {
    int row = blockIdx.x;
    const float4* r4 = (const float4*)(logits + (long)row * D_VOCAB);
    int tid = threadIdx.x;
    const int NV4 = D_VOCAB / 4;

    float m = -1e30f;
    for (int i = tid; i < NV4; i += 256) {
        float4 v = r4[i];
        m = fmaxf(m, fmaxf(fmaxf(v.x, v.y), fmaxf(v.z, v.w)));
    }
    float mx = blk_reduce<1>(m);

    float s = 0.f;
    for (int i = tid; i < NV4; i += 256) {
        float4 v = r4[i];
        s += expf(v.x - mx) + expf(v.y - mx) + expf(v.z - mx) + expf(v.w - mx);
    }
    float sum = blk_reduce<0>(s);

    if (tid == 0)
        nll[row] = (mx + logf(sum)) - logits[(long)row * D_VOCAB + y[row]];
}

__global__ void loss_reduce_kernel(const float* __restrict__ nll, float* __restrict__ out,
                                   long ofs) {
    __shared__ float red[256];
    int tid = threadIdx.x;
    float s = 0.f;
    for (int i = tid; i < BT; i += 256) s += nll[i];
    red[tid] = s; __syncthreads();
    #pragma unroll
    for (int o = 128; o > 0; o >>= 1) { if (tid < o) red[tid] += red[tid + o]; __syncthreads(); }
    if (tid == 0) out[ofs] = red[0] / (float)BT;
}

// ---------------- driver -----------------------------------------------------
extern "C" void kernel_launch(void* const* d_in, const int* in_sizes, int n_in,
                              void* d_out, int out_size) {
    (void)in_sizes; (void)n_in;
    const int*   x   = (const int*)  d_in[0];
    const int*   y   = (const int*)  d_in[1];
    const float* enc = (const float*)d_in[2];
    const float* g1  = (const float*)d_in[3];
    const float* b1  = (const float*)d_in[4];
    const float* wq  = (const float*)d_in[5];
    const float* wk  = (const float*)d_in[6];
    const float* wv  = (const float*)d_in[7];
    const float* g2  = (const float*)d_in[8];
    const float* b2  = (const float*)d_in[9];
    const float* w1  = (const float*)d_in[10];
    const float* bb1 = (const float*)d_in[11];
    const float* w2  = (const float*)d_in[12];
    const float* bb2 = (const float*)d_in[13];
    float* out = (float*)d_out;

    float *z, *o, *s, *nll;
    bf16 *ylnh, *ylnl, *qkh, *qkl, *sh, *sl, *vTh, *vTl, *hh, *hl, *wth, *wtl;
    __half *zf16, *encf16;
    cudaGetSymbolAddress((void**)&z,   g_z);
    cudaGetSymbolAddress((void**)&o,   g_o);
    cudaGetSymbolAddress((void**)&s,   g_s);
    cudaGetSymbolAddress((void**)&nll, g_nll);
    cudaGetSymbolAddress((void**)&ylnh, g_ylnh);
    cudaGetSymbolAddress((void**)&ylnl, g_ylnl);
    cudaGetSymbolAddress((void**)&qkh, g_qkh);
    cudaGetSymbolAddress((void**)&qkl, g_qkl);
    cudaGetSymbolAddress((void**)&sh, g_sh);
    cudaGetSymbolAddress((void**)&sl, g_sl);
    cudaGetSymbolAddress((void**)&vTh, g_vTh);
    cudaGetSymbolAddress((void**)&vTl, g_vTl);
    cudaGetSymbolAddress((void**)&hh, g_hh);
    cudaGetSymbolAddress((void**)&hl, g_hl);
    cudaGetSymbolAddress((void**)&zf16, g_zf16);
    cudaGetSymbolAddress((void**)&encf16, g_encf16);
    cudaGetSymbolAddress((void**)&wth, g_wth);
    cudaGetSymbolAddress((void**)&wtl, g_wtl);

    static int smem_set = 0;
    if (!smem_set) {
        cudaFuncSetAttribute(gemm_bs, cudaFuncAttributeMaxDynamicSharedMemorySize,
                             NSTAGE * STAGE_BYTES);
        cudaFuncSetAttribute(gemm_h1, cudaFuncAttributeMaxDynamicSharedMemorySize,
                             NSTAGE * H_STAGE);
        smem_set = 1;
    }
    const int GS = NSTAGE * STAGE_BYTES;
    const int GH = NSTAGE * H_STAGE;

    const long DD = (long)D_MODEL * D_MODEL;
    const long SD = (long)SEQ * D_MODEL;
    const long SS = (long)SEQ * SEQ;
    const long S2 = (long)SEQ * D2;
    bf16* wvTh = wth + 2 * DD; bf16* wvTl = wtl + 2 * DD;
    bf16* w1Th = wth + 3 * DD; bf16* w1Tl = wtl + 3 * DD;
    bf16* w2Th = wth + 4 * DD; bf16* w2Tl = wtl + 4 * DD;

    dim3 tgrid(D_MODEL / 32, D_MODEL / 32, 1);
    dim3 tblk(32, 8);

    embed_kernel<<<BT, 256>>>(x, enc, z);
    transpose_split<<<tgrid, tblk>>>(wq, wth + 0 * DD, wtl + 0 * DD, D_MODEL, D_MODEL);
    transpose_split<<<tgrid, tblk>>>(wk, wth + 1 * DD, wtl + 1 * DD, D_MODEL, D_MODEL);
    transpose_split<<<tgrid, tblk>>>(wv, wvTh, wvTl, D_MODEL, D_MODEL);

    dim3 grid_qk  (BT / 128, D2 / 128);            // (32, 16)
    dim3 grid_proj(BT / 128, D_MODEL / 128);       // (32, 8)
    dim3 grid_attn(SEQ / 128, SEQ / 128, NB);      // (8, 8, 4)
    dim3 grid_vT  (D_MODEL / 128, SEQ / 128, NB);  // (8, 8, 4)

    for (int layer = 0; layer < NLAYERS; layer++) {
        ln_kernel<<<BT, 256>>>(z, g1, b1, ylnh, ylnl);

        // fused QK: [BT x 2048] = yln @ [wqT; wkT]^T -> split
        gemm_bs<<<grid_qk, 256, GS>>>(ylnh, ylnl, wth, wtl, nullptr, nullptr, qkh, qkl,
                                      D_MODEL, D_MODEL, D2, 0, 0, 0, D_MODEL, 1.f, 8);

        // vT[d, t] = sum_k wvT[d,k] * yln[t,k]  -> split, per-batch
        gemm_bs<<<grid_vT, 256, GS>>>(wvTh, wvTl, ylnh, ylnl, nullptr, nullptr, vTh, vTl,
                                      D_MODEL, D_MODEL, SEQ, 0, SD, SD, D_MODEL, 1.f, 8);

        if (layer == 0) {   // remaining weight prep, overlaps with layer-0 attention
            transpose_split<<<tgrid, tblk>>>(w1, w1Th, w1Tl, D_MODEL, D_MODEL);
            transpose_split<<<tgrid, tblk>>>(w2, w2Th, w2Tl, D_MODEL, D_MODEL);
            tohalf_kernel<<<1024, 256>>>(enc, encf16, (long)D_VOCAB * D_MODEL / 4);
        }

        // S = (Q K^T)/32 -> fp32
        gemm_bs<<<grid_attn, 256, GS>>>(qkh, qkl, qkh + D_MODEL, qkl + D_MODEL,
                                        nullptr, s, nullptr, nullptr,
                                        D2, D2, SEQ, S2, S2, SS, D_MODEL, 0.03125f, 16);

        softmax_kernel<<<NB * SEQ, 256>>>(s, sh, sl);

        // O = S V -> fp32
        gemm_bs<<<grid_attn, 256, GS>>>(sh, sl, vTh, vTl, nullptr, o, nullptr, nullptr,
                                        SEQ, SEQ, D_MODEL, SS, SD, SD, SEQ, 1.f, 16);

        ln_kernel<<<BT, 256>>>(o, g2, b2, ylnh, ylnl);

        gemm_bs<<<grid_proj, 256, GS>>>(ylnh, ylnl, w1Th, w1Tl, bb1, nullptr, hh, hl,
                                        D_MODEL, D_MODEL, D_MODEL, 0, 0, 0, D_MODEL,
                                        1.f, 8 | 4 | 1);
        gemm_bs<<<grid_proj, 256, GS>>>(hh, hl, w2Th, w2Tl, bb2, z, nullptr, nullptr,
                                        D_MODEL, D_MODEL, D_MODEL, 0, 0, 0, D_MODEL,
                                        1.f, 16 | 4 | 2);
    }

    tohalf_kernel<<<512, 256>>>(z, zf16, (long)BT * D_MODEL / 4);

    // logits = Z enc^T in fp16 single-pass (error ~1e-4, non-compounding)
    dim3 grid_logits(BT / 128, D_VOCAB / 128);     // (32, 250)
    gemm_h1<<<grid_logits, 256, GH>>>(zf16, encf16, out, D_MODEL, D_MODEL, D_VOCAB, D_MODEL);

    nll_kernel<<<BT, 256>>>(out, y, nll);
    if ((long)out_size > BTV)
        loss_reduce_kernel<<<1, 256>>>(nll, out, BTV);
}

// round 10
// speedup vs baseline: 2.9946x; 1.9595x over previous
#include <cuda_runtime.h>
#include <cuda_fp16.h>
#include <cstdint>
#include <math.h>

#define D_MODEL 1024
#define D_VOCAB 32000
#define NB 4
#define SEQ 1024
#define BT (NB * SEQ)
#define NLAYERS 6
#define BTV ((long)BT * D_VOCAB)
#define D2 (2 * D_MODEL)

// ---------------- scratch (device globals) ----------------------------------
__device__ float g_z [BT * D_MODEL];
__device__ float g_o [BT * D_MODEL];
__device__ float g_s [NB * SEQ * SEQ];
__device__ float g_nll[BT];

__device__ __half g_ylnf[BT * D_MODEL];
__device__ __half g_qkf [BT * D2];
__device__ __half g_sf  [NB * SEQ * SEQ];
__device__ __half g_vTf [BT * D_MODEL];
__device__ __half g_hf  [BT * D_MODEL];
__device__ __half g_zf  [BT * D_MODEL];
__device__ __half g_encf[(long)D_VOCAB * D_MODEL];
__device__ __half g_wtf [5 * D_MODEL * D_MODEL];   // wqT wkT wvT w1T w2T

// ---------------- helpers ----------------------------------------------------
__device__ __forceinline__ uint32_t smem_u32(const void* p) {
    uint32_t a;
    asm("{ .reg .u64 t; cvta.to.shared.u64 t, %1; cvt.u32.u64 %0, t; }" : "=r"(a) : "l"(p));
    return a;
}
__device__ __forceinline__ void ldsm4(uint32_t addr, uint32_t& r0, uint32_t& r1,
                                      uint32_t& r2, uint32_t& r3) {
    asm volatile("ldmatrix.sync.aligned.m8n8.x4.shared.b16 {%0,%1,%2,%3}, [%4];"
                 : "=r"(r0), "=r"(r1), "=r"(r2), "=r"(r3) : "r"(addr));
}
__device__ __forceinline__ void mma_fp16(float* c, uint32_t a0, uint32_t a1,
                                         uint32_t a2, uint32_t a3,
                                         uint32_t b0, uint32_t b1) {
    asm volatile(
        "mma.sync.aligned.m16n8k16.row.col.f32.f16.f16.f32 "
        "{%0,%1,%2,%3}, {%4,%5,%6,%7}, {%8,%9}, {%0,%1,%2,%3};"
        : "+f"(c[0]), "+f"(c[1]), "+f"(c[2]), "+f"(c[3])
        : "r"(a0), "r"(a1), "r"(a2), "r"(a3), "r"(b0), "r"(b1));
}
#define CP16(dst, src) \
    asm volatile("cp.async.cg.shared.global [%0], [%1], 16;" :: "r"(dst), "l"(src))
#define CP_COMMIT() asm volatile("cp.async.commit_group;" ::: "memory")
#define CP_WAIT1()  asm volatile("cp.async.wait_group 1;" ::: "memory")

// block (256 thr) reduction; op 0 = sum, 1 = max
template <int OP>
__device__ __forceinline__ float blk_reduce(float v) {
    __shared__ float sh[8];
    int tid = threadIdx.x, lane = tid & 31, wid = tid >> 5;
    #pragma unroll
    for (int o = 16; o; o >>= 1) {
        float t = __shfl_xor_sync(0xffffffffu, v, o);
        v = OP ? fmaxf(v, t) : v + t;
    }
    if (lane == 0) sh[wid] = v;
    __syncthreads();
    if (tid == 0) {
        float r = sh[0];
        #pragma unroll
        for (int i = 1; i < 8; i++) r = OP ? fmaxf(r, sh[i]) : r + sh[i];
        sh[0] = r;
    }
    __syncthreads();
    float r = sh[0];
    __syncthreads();
    return r;
}

// ---------------- fp16 single-pass GEMM NT -----------------------------------
// C[m,n] = alpha * sum_k A[m,k]*B[n,k] (fp16 in, fp32 acc)
// flags: 1=relu 2=accum-C-fp32 4=bias 8=fp16-out(Cf) 16=fp32-out(C)
// grid (M/128, N/128, batch), 256 threads. K%32==0.
#define H_STAGE 16384
#define NSTAGE 3
__global__ __launch_bounds__(256, 2) void gemm_h(
    const __half* __restrict__ A, const __half* __restrict__ B,
    const float* __restrict__ bias, float* __restrict__ C,
    __half* __restrict__ Cf,
    int lda, int ldb, int ldc, long sA, long sB, long sC,
    int K, float alpha, int flags) {

    extern __shared__ __align__(16) uint8_t sm[];

    A += (long)blockIdx.z * sA;
    B += (long)blockIdx.z * sB;
    if (C)  C  += (long)blockIdx.z * sC;
    if (Cf) Cf += (long)blockIdx.z * sC;

    const int tid  = threadIdx.x;
    const int wid  = tid >> 5;
    const int lane = tid & 31;
    const int warp_m = wid & 3;
    const int warp_n = wid >> 2;
    const int row0 = blockIdx.x * 128;
    const int col0 = blockIdx.y * 128;

    const uint32_t sbase = smem_u32(sm);

    const int lr = tid >> 1;
    const int lq = tid & 1;
    const int swz = (lr >> 1) & 3;
    const __half* Ap = A + (long)(row0 + lr) * lda;
    const __half* Bp = B + (long)(col0 + lr) * ldb;

    float acc[2][8][4];
    #pragma unroll
    for (int mb = 0; mb < 2; mb++)
        #pragma unroll
        for (int nb = 0; nb < 8; nb++)
            #pragma unroll
            for (int i = 0; i < 4; i++) acc[mb][nb][i] = 0.f;

    auto load_tile = [&](int kt, int st) {
        int k0 = kt << 5;
        uint32_t sb = sbase + st * H_STAGE;
        #pragma unroll
        for (int j = 0; j < 2; j++) {
            int c = lq * 2 + j;
            uint32_t off = (uint32_t)(lr * 64 + (c ^ swz) * 16);
            CP16(sb + off,        Ap + k0 + c * 8);
            CP16(sb + 8192 + off, Bp + k0 + c * 8);
        }
    };

    const int KT = K >> 5;
    load_tile(0, 0); CP_COMMIT();
    if (KT > 1) { load_tile(1, 1); CP_COMMIT(); }
    else        { CP_COMMIT(); }

    for (int kt = 0; kt < KT; kt++) {
        CP_WAIT1();
        __syncthreads();
        if (kt + 2 < KT) load_tile(kt + 2, (kt + 2) % NSTAGE);
        CP_COMMIT();

        uint32_t sb = sbase + (kt % NSTAGE) * H_STAGE;
        #pragma unroll
        for (int kc = 0; kc < 2; kc++) {
            const int chunkA = kc * 2 + (lane >> 4);
            uint32_t ah[2][4];
            #pragma unroll
            for (int mb = 0; mb < 2; mb++) {
                int mrow = warp_m * 32 + mb * 16 + (lane & 15);
                uint32_t off = (uint32_t)(mrow * 64 + (chunkA ^ ((mrow >> 1) & 3)) * 16);
                ldsm4(sb + off, ah[mb][0], ah[mb][1], ah[mb][2], ah[mb][3]);
            }
            #pragma unroll
            for (int nb4 = 0; nb4 < 4; nb4++) {
                int nrow = warp_n * 64 + nb4 * 16 + (lane & 15);
                uint32_t off = (uint32_t)(nrow * 64 + (chunkA ^ ((nrow >> 1) & 3)) * 16);
                uint32_t b0, b1, b2, b3;
                ldsm4(sb + 8192 + off, b0, b1, b2, b3);
                #pragma unroll
                for (int mb = 0; mb < 2; mb++) {
                    mma_fp16(acc[mb][nb4 * 2],     ah[mb][0], ah[mb][1], ah[mb][2], ah[mb][3], b0, b2);
                    mma_fp16(acc[mb][nb4 * 2 + 1], ah[mb][0], ah[mb][1], ah[mb][2], ah[mb][3], b1, b3);
                }
            }
        }
    }

    #pragma unroll
    for (int mb = 0; mb < 2; mb++) {
        #pragma unroll
        for (int nb = 0; nb < 8; nb++) {
            int m0 = row0 + warp_m * 32 + mb * 16 + (lane >> 2);
            int n0 = col0 + warp_n * 64 + nb * 8 + (lane & 3) * 2;
            #pragma unroll
            for (int half = 0; half < 2; half++) {
                int m = m0 + half * 8;
                float v0 = acc[mb][nb][half * 2 + 0] * alpha;
                float v1 = acc[mb][nb][half * 2 + 1] * alpha;
                if (flags & 4) { v0 += bias[n0]; v1 += bias[n0 + 1]; }
                if (flags & 1) { v0 = fmaxf(v0, 0.f); v1 = fmaxf(v1, 0.f); }
                long idx = (long)m * ldc + n0;
                if (flags & 2) { float2 o = *(float2*)(C + idx); v0 += o.x; v1 += o.y; }
                if (flags & 16) *(float2*)(C + idx) = make_float2(v0, v1);
                if (flags & 8)  *(__half2*)(Cf + idx) = __floats2half2_rn(v0, v1);
            }
        }
    }
}

// ---------------- transpose + fp32->fp16 -------------------------------------
__global__ void transpose_half(const float* __restrict__ src, __half* __restrict__ dst,
                               int R, int Ccols) {
    __shared__ float t[32][33];
    long ofs = (long)blockIdx.z * R * Ccols;
    src += ofs; dst += ofs;
    int bx = blockIdx.x * 32, by = blockIdx.y * 32;
    int x = bx + threadIdx.x;
    #pragma unroll
    for (int j = 0; j < 32; j += 8) {
        int y = by + threadIdx.y + j;
        t[threadIdx.y + j][threadIdx.x] = src[(long)y * Ccols + x];
    }
    __syncthreads();
    x = by + threadIdx.x;
    #pragma unroll
    for (int j = 0; j < 32; j += 8) {
        int y = bx + threadIdx.y + j;
        dst[(long)y * R + x] = __float2half_rn(t[threadIdx.x][threadIdx.y + j]);
    }
}

// ---------------- fp32 -> fp16 convert ---------------------------------------
__global__ void tohalf_kernel(const float* __restrict__ src, __half* __restrict__ dst,
                              long n4) {
    long i = (long)blockIdx.x * blockDim.x + threadIdx.x;
    long stride = (long)gridDim.x * blockDim.x;
    for (; i < n4; i += stride) {
        float4 v = ((const float4*)src)[i];
        ((__half2*)dst)[i * 2]     = __floats2half2_rn(v.x, v.y);
        ((__half2*)dst)[i * 2 + 1] = __floats2half2_rn(v.z, v.w);
    }
}

// ---------------- embedding gather ------------------------------------------
__global__ void embed_kernel(const int* __restrict__ x, const float* __restrict__ enc,
                             float* __restrict__ z) {
    int row = blockIdx.x;
    int tok = x[row];
    const float4* src = (const float4*)(enc + (long)tok * D_MODEL);
    float4* dst = (float4*)(z + (long)row * D_MODEL);
    for (int i = threadIdx.x; i < D_MODEL / 4; i += blockDim.x) dst[i] = src[i];
}

// ---------------- (buggy) LayerNorm, single pass -> fp16 ---------------------
__global__ void ln_kernel(const float* __restrict__ in, const float* __restrict__ gamma,
                          const float* __restrict__ beta, __half* __restrict__ outf) {
    int row = blockIdx.x;
    int tid = threadIdx.x;
    float4 xv = ((const float4*)(in + (long)row * D_MODEL))[tid];

    float s  = xv.x + xv.y + xv.z + xv.w;
    float s2 = xv.x * xv.x + xv.y * xv.y + xv.z * xv.z + xv.w * xv.w;
    float S  = blk_reduce<0>(s);
    float S2 = blk_reduce<0>(s2);
    float mu  = S * (1.f / (float)D_MODEL);
    float var = (S2 - (float)D_MODEL * mu * mu) * (1.f / (float)(D_MODEL - 1));
    float shift = mu * rsqrtf(var);

    float4 g = ((const float4*)gamma)[tid];
    float4 b = ((const float4*)beta)[tid];
    long base = (long)row * D_MODEL + tid * 4;
    *(__half2*)(outf + base)     = __floats2half2_rn((xv.x - shift) * g.x + b.x,
                                                     (xv.y - shift) * g.y + b.y);
    *(__half2*)(outf + base + 2) = __floats2half2_rn((xv.z - shift) * g.z + b.z,
                                                     (xv.w - shift) * g.w + b.w);
}

// ---------------- softmax, single pass -> fp16 -------------------------------
__global__ void softmax_kernel(const float* __restrict__ s, __half* __restrict__ outf) {
    int row = blockIdx.x;
    int tid = threadIdx.x;
    float4 v = ((const float4*)(s + (long)row * SEQ))[tid];

    float m = fmaxf(fmaxf(v.x, v.y), fmaxf(v.z, v.w));
    float mx = blk_reduce<1>(m);

    float e0 = expf(v.x - mx), e1 = expf(v.y - mx);
    float e2 = expf(v.z - mx), e3 = expf(v.w - mx);
    float sum = blk_reduce<0>(e0 + e1 + e2 + e3);
    float inv = 1.f / sum;

    long base = (long)row * SEQ + tid * 4;
    *(__half2*)(outf + base)     = __floats2half2_rn(e0 * inv, e1 * inv);
    *(__half2*)(outf + base + 2) = __floats2half2_rn(e2 * inv, e3 * inv);
}

// ---------------- per-row NLL over V=32000 (float4) --------------------------
__global__ void nll_kernel(const float* __restrict__ logits, const int* __restrict__ y,
                           float* __restrict__ nll) {
    int row = blockIdx.x;
    const float4* r4 = (const float4*)(logits + (long)row * D_VOCAB);
    int tid = threadIdx.x;
    const int NV4 = D_VOCAB / 4;

    float m = -1e30f;
    for (int i = tid; i < NV4; i += 256) {
        float4 v = r4[i];
        m = fmaxf(m, fmaxf(fmaxf(v.x, v.y), fmaxf(v.z, v.w)));
    }
    float mx = blk_reduce<1>(m);

    float s = 0.f;
    for (int i = tid; i < NV4; i += 256) {
        float4 v = r4[i];
        s += expf(v.x - mx) + expf(v.y - mx) + expf(v.z - mx) + expf(v.w - mx);
    }
    float sum = blk_reduce<0>(s);

    if (tid == 0)
        nll[row] = (mx + logf(sum)) - logits[(long)row * D_VOCAB + y[row]];
}

__global__ void loss_reduce_kernel(const float* __restrict__ nll, float* __restrict__ out,
                                   long ofs) {
    __shared__ float red[256];
    int tid = threadIdx.x;
    float s = 0.f;
    for (int i = tid; i < BT; i += 256) s += nll[i];
    red[tid] = s; __syncthreads();
    #pragma unroll
    for (int o = 128; o > 0; o >>= 1) { if (tid < o) red[tid] += red[tid + o]; __syncthreads(); }
    if (tid == 0) out[ofs] = red[0] / (float)BT;
}

// ---------------- driver -----------------------------------------------------
extern "C" void kernel_launch(void* const* d_in, const int* in_sizes, int n_in,
                              void* d_out, int out_size) {
    (void)in_sizes; (void)n_in;
    const int*   x   = (const int*)  d_in[0];
    const int*   y   = (const int*)  d_in[1];
    const float* enc = (const float*)d_in[2];
    const float* g1  = (const float*)d_in[3];
    const float* b1  = (const float*)d_in[4];
    const float* wq  = (const float*)d_in[5];
    const float* wk  = (const float*)d_in[6];
    const float* wv  = (const float*)d_in[7];
    const float* g2  = (const float*)d_in[8];
    const float* b2  = (const float*)d_in[9];
    const float* w1  = (const float*)d_in[10];
    const float* bb1 = (const float*)d_in[11];
    const float* w2  = (const float*)d_in[12];
    const float* bb2 = (const float*)d_in[13];
    float* out = (float*)d_out;

    float *z, *o, *s, *nll;
    __half *ylnf, *qkf, *sf, *vTf, *hf, *zf, *encf, *wtf;
    cudaGetSymbolAddress((void**)&z,   g_z);
    cudaGetSymbolAddress((void**)&o,   g_o);
    cudaGetSymbolAddress((void**)&s,   g_s);
    cudaGetSymbolAddress((void**)&nll, g_nll);
    cudaGetSymbolAddress((void**)&ylnf, g_ylnf);
    cudaGetSymbolAddress((void**)&qkf, g_qkf);
    cudaGetSymbolAddress((void**)&sf, g_sf);
    cudaGetSymbolAddress((void**)&vTf, g_vTf);
    cudaGetSymbolAddress((void**)&hf, g_hf);
    cudaGetSymbolAddress((void**)&zf, g_zf);
    cudaGetSymbolAddress((void**)&encf, g_encf);
    cudaGetSymbolAddress((void**)&wtf, g_wtf);

    static int smem_set = 0;
    if (!smem_set) {
        cudaFuncSetAttribute(gemm_h, cudaFuncAttributeMaxDynamicSharedMemorySize,
                             NSTAGE * H_STAGE);
        smem_set = 1;
    }
    const int GH = NSTAGE * H_STAGE;

    const long DD = (long)D_MODEL * D_MODEL;
    const long SD = (long)SEQ * D_MODEL;
    const long SS = (long)SEQ * SEQ;
    const long S2 = (long)SEQ * D2;
    __half* wvTf = wtf + 2 * DD;
    __half* w1Tf = wtf + 3 * DD;
    __half* w2Tf = wtf + 4 * DD;

    dim3 tgrid(D_MODEL / 32, D_MODEL / 32, 1);
    dim3 tblk(32, 8);

    embed_kernel<<<BT, 256>>>(x, enc, z);
    transpose_half<<<tgrid, tblk>>>(wq, wtf + 0 * DD, D_MODEL, D_MODEL);
    transpose_half<<<tgrid, tblk>>>(wk, wtf + 1 * DD, D_MODEL, D_MODEL);
    transpose_half<<<tgrid, tblk>>>(wv, wvTf, D_MODEL, D_MODEL);
    transpose_half<<<tgrid, tblk>>>(w1, w1Tf, D_MODEL, D_MODEL);
    transpose_half<<<tgrid, tblk>>>(w2, w2Tf, D_MODEL, D_MODEL);
    tohalf_kernel<<<1024, 256>>>(enc, encf, (long)D_VOCAB * D_MODEL / 4);

    dim3 grid_qk  (BT / 128, D2 / 128);            // (32, 16)
    dim3 grid_proj(BT / 128, D_MODEL / 128);       // (32, 8)
    dim3 grid_attn(SEQ / 128, SEQ / 128, NB);      // (8, 8, 4)
    dim3 grid_vT  (D_MODEL / 128, SEQ / 128, NB);  // (8, 8, 4)

    for (int layer = 0; layer < NLAYERS; layer++) {
        ln_kernel<<<BT, 256>>>(z, g1, b1, ylnf);

        // fused QK: [BT x 2048] = yln @ [wqT; wkT]^T -> fp16
        gemm_h<<<grid_qk, 256, GH>>>(ylnf, wtf, nullptr, nullptr, qkf,
                                     D_MODEL, D_MODEL, D2, 0, 0, 0, D_MODEL, 1.f, 8);

        // vT[d, t] = sum_k wvT[d,k] * yln[t,k]  -> fp16, per-batch
        gemm_h<<<grid_vT, 256, GH>>>(wvTf, ylnf, nullptr, nullptr, vTf,
                                     D_MODEL, D_MODEL, SEQ, 0, SD, SD, D_MODEL, 1.f, 8);

        // S = (Q K^T)/32 -> fp32
        gemm_h<<<grid_attn, 256, GH>>>(qkf, qkf + D_MODEL, nullptr, s, nullptr,
                                       D2, D2, SEQ, S2, S2, SS, D_MODEL, 0.03125f, 16);

        softmax_kernel<<<NB * SEQ, 256>>>(s, sf);

        // O = S V -> fp32
        gemm_h<<<grid_attn, 256, GH>>>(sf, vTf, nullptr, o, nullptr,
                                       SEQ, SEQ, D_MODEL, SS, SD, SD, SEQ, 1.f, 16);

        ln_kernel<<<BT, 256>>>(o, g2, b2, ylnf);

        // H = relu(Y W1 + b1) -> fp16
        gemm_h<<<grid_proj, 256, GH>>>(ylnf, w1Tf, bb1, nullptr, hf,
                                       D_MODEL, D_MODEL, D_MODEL, 0, 0, 0, D_MODEL,
                                       1.f, 8 | 4 | 1);
        // Z += H W2 + b2 -> fp32 accumulate
        gemm_h<<<grid_proj, 256, GH>>>(hf, w2Tf, bb2, z, nullptr,
                                       D_MODEL, D_MODEL, D_MODEL, 0, 0, 0, D_MODEL,
                                       1.f, 16 | 4 | 2);
    }

    tohalf_kernel<<<512, 256>>>(z, zf, (long)BT * D_MODEL / 4);

    // logits = Z enc^T -> fp32
    dim3 grid_logits(BT / 128, D_VOCAB / 128);     // (32, 250)
    gemm_h<<<grid_logits, 256, GH>>>(zf, encf, nullptr, out, nullptr,
                                     D_MODEL, D_MODEL, D_VOCAB, 0, 0, 0, D_MODEL, 1.f, 16);

    nll_kernel<<<BT, 256>>>(out, y, nll);
    if ((long)out_size > BTV)
        loss_reduce_kernel<<<1, 256>>>(nll, out, BTV);
}